// round 12
// baseline (speedup 1.0000x reference)
#include <cuda_runtime.h>
#include <math.h>
#include <stdint.h>

#define NBn 65536
#define NE  1048576
#define Bg  128
#define Nn  512
#define KK1 410
#define KK2 205
#define KK3 103
#define FD  128

// packed fp32x2 FMA: d = a*b + c on both halves (SASS FFMA2)
#define FMA_F32X2(d, a, b, c) \
    asm("fma.rn.f32x2 %0, %1, %2, %3;" : "=l"(d) : "l"(a), "l"(b), "l"(c))
#define PACK_F32X2(out, lo, hi) \
    asm("mov.b64 %0, {%1, %2};" : "=l"(out) : "f"(lo), "f"(hi))
#define UNPACK_F32X2(lo, hi, in) \
    asm("mov.b64 {%0, %1}, %2;" : "=f"(lo), "=f"(hi) : "l"(in))

// ---------------- device global scratch ----------------
__device__ float d_agg[NBn * FD];
__device__ float d_xa [NBn * FD];
__device__ float d_xb [NBn * FD];
__device__ float d_xs [NBn * FD];
__device__ float d_xc [NBn * FD];
__device__ float d_score[NBn];
__device__ float d_t[NBn];
__device__ float d_r[NBn];
__device__ unsigned char d_nmask[NBn];
__device__ int   d_hist[NBn];
__device__ int   d_rowptr[NBn + 1];
__device__ int   d_posA[NBn];
__device__ int   d_bsum[256];
__device__ int   d_bsumx[256];
__device__ int2  d_se[NE];
__device__ float d_als[NBn * 4];
__device__ float d_ald[NBn * 4];
__device__ float d_ale[(size_t)NE * 4];
__device__ float d_V[28];
__device__ float d_alse[4];
__device__ float d_easum[8];
__device__ float d_gap[3 * Bg * FD];
__device__ float d_p1norm;

__device__ __forceinline__ float* getbuf(int id, const float* ext) {
    switch (id) {
        case 0: return d_agg;
        case 1: return d_xa;
        case 2: return d_xb;
        case 3: return d_xs;
        case 4: return d_xc;
        default: return (float*)ext;
    }
}

// ---------------- small utility kernels ----------------
__global__ void k_zero_hist() {
    int i = blockIdx.x * blockDim.x + threadIdx.x;
    if (i < NBn) d_hist[i] = 0;
}
__global__ void k_init_mask() {
    int i = blockIdx.x * blockDim.x + threadIdx.x;
    if (i < NBn) d_nmask[i] = 1;
}

// ---------------- CSR build ----------------
__global__ void k_hist(const int* __restrict__ dst) {
    int e = blockIdx.x * blockDim.x + threadIdx.x;
    if (e < NE) atomicAdd(&d_hist[dst[e]], 1);
}

__global__ void k_bsum() {
    int t = threadIdx.x;
    int v = d_hist[blockIdx.x * 256 + t];
    int lane = t & 31, w = t >> 5;
#pragma unroll
    for (int o = 16; o; o >>= 1) v += __shfl_down_sync(0xffffffffu, v, o);
    __shared__ int ws[8];
    if (lane == 0) ws[w] = v;
    __syncthreads();
    if (t == 0) {
        int s = 0;
#pragma unroll
        for (int i = 0; i < 8; i++) s += ws[i];
        d_bsum[blockIdx.x] = s;
    }
}

__global__ void k_scanb() {
    int t = threadIdx.x;
    int v = d_bsum[t];
    int lane = t & 31, w = t >> 5;
    int x = v;
#pragma unroll
    for (int o = 1; o < 32; o <<= 1) {
        int y = __shfl_up_sync(0xffffffffu, x, o);
        if (lane >= o) x += y;
    }
    __shared__ int ws[8];
    if (lane == 31) ws[w] = x;
    __syncthreads();
    __shared__ int wx[8];
    if (t == 0) {
        int run = 0;
#pragma unroll
        for (int i = 0; i < 8; i++) { wx[i] = run; run += ws[i]; }
    }
    __syncthreads();
    d_bsumx[t] = wx[w] + x - v;
    if (t == 0) d_rowptr[NBn] = NE;
}

__global__ void k_scan2() {
    int t = threadIdx.x;
    int i = blockIdx.x * 256 + t;
    int v = d_hist[i];
    int lane = t & 31, w = t >> 5;
    int x = v;
#pragma unroll
    for (int o = 1; o < 32; o <<= 1) {
        int y = __shfl_up_sync(0xffffffffu, x, o);
        if (lane >= o) x += y;
    }
    __shared__ int ws[8];
    if (lane == 31) ws[w] = x;
    __syncthreads();
    __shared__ int wx[8];
    if (t == 0) {
        int run = 0;
#pragma unroll
        for (int j = 0; j < 8; j++) { wx[j] = run; run += ws[j]; }
    }
    __syncthreads();
    int excl = d_bsumx[blockIdx.x] + wx[w] + x - v;
    d_rowptr[i] = excl;
    d_posA[i]   = excl;
}

__global__ void k_scatter(const int* __restrict__ src, const int* __restrict__ dst) {
    int e = blockIdx.x * blockDim.x + threadIdx.x;
    if (e >= NE) return;
    int p = atomicAdd(&d_posA[dst[e]], 1);
    d_se[p] = make_int2(src[e], e);
}

// ---------------- SAGE mean aggregation ----------------
// 2 warps per dst: each warp owns a 64-column half-row (float2 per lane).
// Doubles outstanding loads per SM; cnt redundantly computed by both halves.
__global__ void k_aggmean(int xid, const float* __restrict__ xext, int use_mask) {
    int gw = (blockIdx.x * blockDim.x + threadIdx.x) >> 5;
    int w = gw >> 1;
    int half = gw & 1;
    int lane = threadIdx.x & 31;
    if (w >= NBn) return;
    int coff = half * 64 + lane * 2;
    const float* X = getbuf(xid, xext) + coff;
    float2 a = make_float2(0.f, 0.f);
    float cnt = 0.f;
    if (!use_mask || d_nmask[w]) {
        int b = d_rowptr[w], e = d_rowptr[w + 1];
        int i = b;
        for (; i + 1 < e; i += 2) {
            int s0 = d_se[i].x, s1 = d_se[i + 1].x;
            bool l0 = !use_mask || d_nmask[s0];
            bool l1 = !use_mask || d_nmask[s1];
            float2 v0, v1;
            if (l0) v0 = *(const float2*)(X + (size_t)s0 * FD);
            if (l1) v1 = *(const float2*)(X + (size_t)s1 * FD);
            if (l0) { a.x += v0.x; a.y += v0.y; cnt += 1.f; }
            if (l1) { a.x += v1.x; a.y += v1.y; cnt += 1.f; }
        }
        if (i < e) {
            int s0 = d_se[i].x;
            if (!use_mask || d_nmask[s0]) {
                float2 v0 = *(const float2*)(X + (size_t)s0 * FD);
                a.x += v0.x; a.y += v0.y; cnt += 1.f;
            }
        }
    }
    float inv = 1.f / fmaxf(cnt, 1.f);
    a.x *= inv; a.y *= inv;
    *(float2*)(d_agg + (size_t)w * FD + coff) = a;
}

// ---------------- GEMM with fused epilogues ----------------
// smode 0: none; 1: d_score = tanh(row.sw1 / p1norm); 2: d_t = row.sw1, d_r = row.sw2
// as_w/ad_w: per-head GAT attention dots (width-8 reduce)
__global__ __launch_bounds__(256) void k_gemm(
    int a0id, const float* __restrict__ a0ext, const float* __restrict__ W0,
    int a1id, const float* __restrict__ a1ext, const float* __restrict__ W1,
    const float* __restrict__ bias, int cid, int ktiles, int dorelu,
    const float* __restrict__ as_w, const float* __restrict__ ad_w,
    const float* __restrict__ sw1, const float* __restrict__ sw2, int smode)
{
    __shared__ float As_t[32][66];
    __shared__ float Bs[32][128];
    int tid = threadIdx.x;
    int m0 = blockIdx.x * 64;
    int cx = tid & 31, ry = tid >> 5;

    unsigned long long acc[4][4];
    {
        unsigned long long z;
        PACK_F32X2(z, 0.f, 0.f);
#pragma unroll
        for (int p = 0; p < 4; p++)
#pragma unroll
            for (int j = 0; j < 4; j++) acc[p][j] = z;
    }

    for (int kt = 0; kt < ktiles; kt++) {
        const float* A; const float* W; int kl;
        if (kt < 4) { A = getbuf(a0id, a0ext); W = W0; kl = kt * 32; }
        else        { A = getbuf(a1id, a1ext); W = W1; kl = (kt - 4) * 32; }
#pragma unroll
        for (int r = 0; r < 2; r++) {
            int id = tid + 256 * r;
            int m = id >> 3, k4 = id & 7;
            float4 v = *(const float4*)&A[(size_t)(m0 + m) * FD + kl + k4 * 4];
            As_t[k4 * 4 + 0][m] = v.x;
            As_t[k4 * 4 + 1][m] = v.y;
            As_t[k4 * 4 + 2][m] = v.z;
            As_t[k4 * 4 + 3][m] = v.w;
        }
#pragma unroll
        for (int r = 0; r < 4; r++) {
            int id = tid + 256 * r;          // 1024 float4s total
            int kk = id >> 5, n4 = id & 31;
            *(float4*)&Bs[kk][n4 * 4] =
                *(const float4*)&W[(size_t)(kl + kk) * FD + n4 * 4];
        }
        __syncthreads();
#pragma unroll
        for (int kk = 0; kk < 32; kk++) {
            float4 bv = *(const float4*)&Bs[kk][cx * 4];
            unsigned long long bb0, bb1, bb2, bb3;
            PACK_F32X2(bb0, bv.x, bv.x);
            PACK_F32X2(bb1, bv.y, bv.y);
            PACK_F32X2(bb2, bv.z, bv.z);
            PACK_F32X2(bb3, bv.w, bv.w);
#pragma unroll
            for (int p = 0; p < 4; p++) {
                unsigned long long aa =
                    *(const unsigned long long*)&As_t[kk][ry * 8 + 2 * p];
                FMA_F32X2(acc[p][0], aa, bb0, acc[p][0]);
                FMA_F32X2(acc[p][1], aa, bb1, acc[p][1]);
                FMA_F32X2(acc[p][2], aa, bb2, acc[p][2]);
                FMA_F32X2(acc[p][3], aa, bb3, acc[p][3]);
            }
        }
        __syncthreads();
    }
    int c0 = cx * 4;
    float b0 = 0.f, b1 = 0.f, b2 = 0.f, b3 = 0.f;
    if (bias) { b0 = bias[c0]; b1 = bias[c0 + 1]; b2 = bias[c0 + 2]; b3 = bias[c0 + 3]; }
    float aw0 = 0.f, aw1 = 0.f, aw2 = 0.f, aw3 = 0.f, dw0 = 0.f, dw1 = 0.f, dw2 = 0.f, dw3 = 0.f;
    if (as_w) {
        aw0 = as_w[c0]; aw1 = as_w[c0 + 1]; aw2 = as_w[c0 + 2]; aw3 = as_w[c0 + 3];
        dw0 = ad_w[c0]; dw1 = ad_w[c0 + 1]; dw2 = ad_w[c0 + 2]; dw3 = ad_w[c0 + 3];
    }
    float s10 = 0.f, s11 = 0.f, s12 = 0.f, s13 = 0.f, s20 = 0.f, s21 = 0.f, s22 = 0.f, s23 = 0.f;
    if (smode) {
        s10 = sw1[c0]; s11 = sw1[c0 + 1]; s12 = sw1[c0 + 2]; s13 = sw1[c0 + 3];
        if (smode == 2) { s20 = sw2[c0]; s21 = sw2[c0 + 1]; s22 = sw2[c0 + 2]; s23 = sw2[c0 + 3]; }
    }
    int h = cx >> 3;
    float* C = getbuf(cid, nullptr);
#pragma unroll
    for (int p = 0; p < 4; p++) {
        size_t me = m0 + ry * 8 + 2 * p;
        float4 oe, oo;
        UNPACK_F32X2(oe.x, oo.x, acc[p][0]);
        UNPACK_F32X2(oe.y, oo.y, acc[p][1]);
        UNPACK_F32X2(oe.z, oo.z, acc[p][2]);
        UNPACK_F32X2(oe.w, oo.w, acc[p][3]);
        oe.x += b0; oe.y += b1; oe.z += b2; oe.w += b3;
        oo.x += b0; oo.y += b1; oo.z += b2; oo.w += b3;
        if (dorelu) {
            oe.x = fmaxf(oe.x, 0.f); oe.y = fmaxf(oe.y, 0.f);
            oe.z = fmaxf(oe.z, 0.f); oe.w = fmaxf(oe.w, 0.f);
            oo.x = fmaxf(oo.x, 0.f); oo.y = fmaxf(oo.y, 0.f);
            oo.z = fmaxf(oo.z, 0.f); oo.w = fmaxf(oo.w, 0.f);
        }
        *(float4*)&C[me * FD + c0] = oe;
        *(float4*)&C[(me + 1) * FD + c0] = oo;
        if (as_w) {
            float pae = oe.x * aw0 + oe.y * aw1 + oe.z * aw2 + oe.w * aw3;
            float pao = oo.x * aw0 + oo.y * aw1 + oo.z * aw2 + oo.w * aw3;
            float pde = oe.x * dw0 + oe.y * dw1 + oe.z * dw2 + oe.w * dw3;
            float pdo = oo.x * dw0 + oo.y * dw1 + oo.z * dw2 + oo.w * dw3;
#pragma unroll
            for (int o = 4; o; o >>= 1) {
                pae += __shfl_down_sync(0xffffffffu, pae, o, 8);
                pao += __shfl_down_sync(0xffffffffu, pao, o, 8);
                pde += __shfl_down_sync(0xffffffffu, pde, o, 8);
                pdo += __shfl_down_sync(0xffffffffu, pdo, o, 8);
            }
            if ((cx & 7) == 0) {
                d_als[me * 4 + h] = pae;
                d_als[(me + 1) * 4 + h] = pao;
                d_ald[me * 4 + h] = pde;
                d_ald[(me + 1) * 4 + h] = pdo;
            }
        }
        if (smode) {
            float p1e = oe.x * s10 + oe.y * s11 + oe.z * s12 + oe.w * s13;
            float p1o = oo.x * s10 + oo.y * s11 + oo.z * s12 + oo.w * s13;
            float p2e = oe.x * s20 + oe.y * s21 + oe.z * s22 + oe.w * s23;
            float p2o = oo.x * s20 + oo.y * s21 + oo.z * s22 + oo.w * s23;
#pragma unroll
            for (int o = 16; o; o >>= 1) {
                p1e += __shfl_down_sync(0xffffffffu, p1e, o);
                p1o += __shfl_down_sync(0xffffffffu, p1o, o);
                p2e += __shfl_down_sync(0xffffffffu, p2e, o);
                p2o += __shfl_down_sync(0xffffffffu, p2o, o);
            }
            if (cx == 0) {
                if (smode == 1) {
                    float inv = 1.f / d_p1norm;
                    d_score[me] = tanhf(p1e * inv);
                    d_score[me + 1] = tanhf(p1o * inv);
                } else {
                    d_t[me] = p1e; d_t[me + 1] = p1o;
                    d_r[me] = p2e; d_r[me + 1] = p2o;
                }
            }
        }
    }
}

__global__ void k_p1norm(const float* __restrict__ w) {  // <<<1,128>>>
    __shared__ float sm[128];
    int t = threadIdx.x;
    float v = w[t];
    sm[t] = v * v;
    __syncthreads();
    for (int o = 64; o; o >>= 1) { if (t < o) sm[t] += sm[t + o]; __syncthreads(); }
    if (t == 0) d_p1norm = sqrtf(sm[0]);
}

// GraphConv score: tanh( sum_{live e->d} t[src] + brel + r[d] )
__global__ void k_gconv(const float* __restrict__ brel) {
    int d = (blockIdx.x * blockDim.x + threadIdx.x) >> 5;
    int lane = threadIdx.x & 31;
    if (d >= NBn) return;
    float a = 0.f;
    if (d_nmask[d]) {
        int b = d_rowptr[d], e = d_rowptr[d + 1];
        for (int i = b + lane; i < e; i += 32) {
            int s = d_se[i].x;
            if (d_nmask[s]) a += d_t[s];
        }
    }
#pragma unroll
    for (int o = 16; o; o >>= 1) a += __shfl_down_sync(0xffffffffu, a, o);
    if (lane == 0) d_score[d] = tanhf(a + brel[0] + d_r[d]);
}

// ---------------- top-k pool (block per graph, 512 threads) ----------------
__global__ __launch_bounds__(512) void k_pool(int xid, int K, int stage) {
    int g = blockIdx.x;
    int t = threadIdx.x;
    int tx = t & 127, ty = t >> 7;
    __shared__ float s[Nn];
    __shared__ unsigned char sel[Nn];
    {
        int n = g * Nn + t;
        s[t] = d_nmask[n] ? d_score[n] : -INFINITY;
    }
    __syncthreads();
    {
        float si = s[t];
        int rank = 0;
        for (int j = 0; j < Nn; j++) {
            float sj = s[j];
            rank += (sj > si) || ((sj == si) && (j < t));
        }
        int se = (rank < K) ? 1 : 0;
        sel[t] = (unsigned char)se;
        d_nmask[g * Nn + t] = (unsigned char)se;
    }
    __syncthreads();
    float* X = getbuf(xid, nullptr);
    float acc = 0.f;
    for (int n = ty; n < Nn; n += 4) {
        size_t idx = (size_t)(g * Nn + n) * FD + tx;
        float v = sel[n] ? X[idx] * s[n] : 0.f;
        X[idx] = v;
        acc += v;
    }
    __shared__ float gs[4][128];
    gs[ty][tx] = acc;
    __syncthreads();
    if (ty == 0)
        d_gap[stage * Bg * FD + g * FD + tx] =
            (gs[0][tx] + gs[1][tx] + gs[2][tx] + gs[3][tx]) / (float)K;
}

// ---------------- GAT ----------------
__global__ void k_vmat(const float* __restrict__ gwe, const float* __restrict__ gae) {  // <<<1,32>>>
    int lane = threadIdx.x;
    if (lane < 8) d_easum[lane] = 0.f;
    for (int o = 0; o < 28; o++) {
        int ed = o >> 2, h = o & 3;
        float p = gwe[ed * FD + h * 32 + lane] * gae[h * 32 + lane];
#pragma unroll
        for (int off = 16; off; off >>= 1) p += __shfl_down_sync(0xffffffffu, p, off);
        if (lane == 0) d_V[ed * 4 + h] = p;
    }
}
__global__ void k_ale(const float* __restrict__ ea) {
    int e = blockIdx.x * blockDim.x + threadIdx.x;
    if (e >= NE) return;
    float at[7];
#pragma unroll
    for (int ed = 0; ed < 7; ed++) at[ed] = ea[(size_t)e * 7 + ed];
#pragma unroll
    for (int h = 0; h < 4; h++) {
        float a = 0.f;
#pragma unroll
        for (int ed = 0; ed < 7; ed++) a += at[ed] * d_V[ed * 4 + h];
        d_ale[(size_t)e * 4 + h] = a;
    }
}
__global__ void k_easum(const float* __restrict__ ea, const int* __restrict__ src,
                        const int* __restrict__ dst) {
    float loc[8];
#pragma unroll
    for (int k = 0; k < 8; k++) loc[k] = 0.f;
    for (int e = blockIdx.x * blockDim.x + threadIdx.x; e < NE; e += gridDim.x * blockDim.x) {
        if (d_nmask[src[e]] && d_nmask[dst[e]]) {
#pragma unroll
            for (int ed = 0; ed < 7; ed++) loc[ed] += ea[(size_t)e * 7 + ed];
            loc[7] += 1.f;
        }
    }
    int lane = threadIdx.x & 31;
#pragma unroll
    for (int k = 0; k < 8; k++) {
        float v = loc[k];
#pragma unroll
        for (int o = 16; o; o >>= 1) v += __shfl_down_sync(0xffffffffu, v, o);
        if (lane == 0) atomicAdd(&d_easum[k], v);
    }
}
__global__ void k_alse() {  // <<<1,32>>>
    int lane = threadIdx.x;
    if (lane < 4) {
        float c = fmaxf(d_easum[7], 1.f);
        float a = 0.f;
#pragma unroll
        for (int ed = 0; ed < 7; ed++) a += (d_easum[ed] / c) * d_V[ed * 4 + lane];
        d_alse[lane] = a;
    }
}

// warp per dst; online softmax; each lane owns 4 columns of head (lane>>3);
// fused p3 score dots (d_t, d_r) in the epilogue
__global__ void k_gat(const float* __restrict__ gb,
                      const float* __restrict__ w1, const float* __restrict__ w2) {
    int d = (blockIdx.x * blockDim.x + threadIdx.x) >> 5;
    int lane = threadIdx.x & 31;
    if (d >= NBn) return;
    int h = lane >> 3;
    float m = -INFINITY, den = 0.f;
    float4 acc = make_float4(0.f, 0.f, 0.f, 0.f);
    bool dal = d_nmask[d] != 0;
    float aldL = (lane < 4) ? d_ald[d * 4 + lane] : 0.f;
    if (dal) {
        int b = d_rowptr[d], e2 = d_rowptr[d + 1];
        for (int i = b; i < e2; i++) {
            int2 se = d_se[i];
            int s = se.x;
            if (!d_nmask[s]) continue;
            int e = se.y;
            float tl = 0.f;
            if (lane < 4) {
                tl = d_als[s * 4 + lane] + aldL + d_ale[(size_t)e * 4 + lane];
                tl = tl > 0.f ? tl : 0.2f * tl;
            }
            float aj = __shfl_sync(0xffffffffu, tl, h);
            float4 xv = *(const float4*)(d_xs + (size_t)s * FD + lane * 4);
            if (aj > m) {
                float sc = __expf(m - aj);
                den = den * sc + 1.f;
                acc.x = acc.x * sc + xv.x;
                acc.y = acc.y * sc + xv.y;
                acc.z = acc.z * sc + xv.z;
                acc.w = acc.w * sc + xv.w;
                m = aj;
            } else {
                float c = __expf(aj - m);
                den += c;
                acc.x += c * xv.x;
                acc.y += c * xv.y;
                acc.z += c * xv.z;
                acc.w += c * xv.w;
            }
        }
        // self loop
        float tl = 0.f;
        if (lane < 4) {
            tl = d_als[d * 4 + lane] + aldL + d_alse[lane];
            tl = tl > 0.f ? tl : 0.2f * tl;
        }
        float aj = __shfl_sync(0xffffffffu, tl, h);
        float4 xv = *(const float4*)(d_xs + (size_t)d * FD + lane * 4);
        if (aj > m) {
            float sc = __expf(m - aj);
            den = den * sc + 1.f;
            acc.x = acc.x * sc + xv.x;
            acc.y = acc.y * sc + xv.y;
            acc.z = acc.z * sc + xv.z;
            acc.w = acc.w * sc + xv.w;
            m = aj;
        } else {
            float c = __expf(aj - m);
            den += c;
            acc.x += c * xv.x;
            acc.y += c * xv.y;
            acc.z += c * xv.z;
            acc.w += c * xv.w;
        }
    }
    float invd = 1.f / fmaxf(den, 1e-16f);
    float4 bb = *(const float4*)(gb + lane * 4);
    float4 o;
    o.x = fmaxf(acc.x * invd + bb.x, 0.f);
    o.y = fmaxf(acc.y * invd + bb.y, 0.f);
    o.z = fmaxf(acc.z * invd + bb.z, 0.f);
    o.w = fmaxf(acc.w * invd + bb.w, 0.f);
    *(float4*)(d_xc + (size_t)d * FD + lane * 4) = o;
    // fused p3 score dots
    float4 wv1 = *(const float4*)(w1 + lane * 4);
    float4 wv2 = *(const float4*)(w2 + lane * 4);
    float p1 = o.x * wv1.x + o.y * wv1.y + o.z * wv1.z + o.w * wv1.w;
    float p2 = o.x * wv2.x + o.y * wv2.y + o.z * wv2.z + o.w * wv2.w;
#pragma unroll
    for (int off = 16; off; off >>= 1) {
        p1 += __shfl_down_sync(0xffffffffu, p1, off);
        p2 += __shfl_down_sync(0xffffffffu, p2, off);
    }
    if (lane == 0) { d_t[d] = p1; d_r[d] = p2; }
}

// ---------------- head MLP (block per graph) ----------------
__global__ void k_head(const float* __restrict__ l1w, const float* __restrict__ l1b,
                       const float* __restrict__ l2w, const float* __restrict__ l2b,
                       const float* __restrict__ l3w, const float* __restrict__ l3b,
                       float* __restrict__ out) {
    int g = blockIdx.x;
    int t = threadIdx.x;
    __shared__ float h[128], h2[128], h3[64];
    h[t] = d_gap[g * FD + t] + d_gap[Bg * FD + g * FD + t] + d_gap[2 * Bg * FD + g * FD + t];
    __syncthreads();
    float a = l1b[t];
    for (int k = 0; k < 128; k++) a += h[k] * l1w[k * 128 + t];
    h2[t] = fmaxf(a, 0.f);
    __syncthreads();
    if (t < 64) {
        float a2 = l2b[t];
        for (int k = 0; k < 128; k++) a2 += h2[k] * l2w[k * 64 + t];
        h3[t] = fmaxf(a2, 0.f);
    }
    __syncthreads();
    if (t == 0) {
        float z = l3b[0];
        for (int k = 0; k < 64; k++) z += h3[k] * l3w[k];
        out[g] = 1.f / (1.f + expf(-z));
    }
}

// ---------------- launch ----------------
extern "C" void kernel_launch(void* const* d_in, const int* in_sizes, int n_in,
                              void* d_out, int out_size) {
    const float* x      = (const float*)d_in[0];
    const int*   ei     = (const int*)d_in[1];
    const float* ea     = (const float*)d_in[2];
    const float* c1_wl  = (const float*)d_in[3];
    const float* c1_bl  = (const float*)d_in[4];
    const float* c1_wr  = (const float*)d_in[5];
    const float* p1_w   = (const float*)d_in[6];
    const float* c2_wl  = (const float*)d_in[7];
    const float* c2_bl  = (const float*)d_in[8];
    const float* c2_wr  = (const float*)d_in[9];
    const float* p2_wrel= (const float*)d_in[10];
    const float* p2_brel= (const float*)d_in[11];
    const float* p2_wroot=(const float*)d_in[12];
    const float* g_w    = (const float*)d_in[13];
    const float* g_as   = (const float*)d_in[14];
    const float* g_ad   = (const float*)d_in[15];
    const float* g_we   = (const float*)d_in[16];
    const float* g_ae   = (const float*)d_in[17];
    const float* g_b    = (const float*)d_in[18];
    const float* p3_wrel= (const float*)d_in[19];
    const float* p3_brel= (const float*)d_in[20];
    const float* p3_wroot=(const float*)d_in[21];
    const float* l1_w   = (const float*)d_in[22];
    const float* l1_b   = (const float*)d_in[23];
    const float* l2_w   = (const float*)d_in[24];
    const float* l2_b   = (const float*)d_in[25];
    const float* l3_w   = (const float*)d_in[26];
    const float* l3_b   = (const float*)d_in[27];
    const int* src = ei;
    const int* dst = ei + NE;
    float* out = (float*)d_out;

    // CSR build (parallel 3-phase scan)
    k_zero_hist<<<NBn / 256, 256>>>();
    k_init_mask<<<NBn / 256, 256>>>();
    k_hist<<<NE / 256, 256>>>(dst);
    k_bsum<<<256, 256>>>();
    k_scanb<<<1, 256>>>();
    k_scan2<<<256, 256>>>();
    k_scatter<<<NE / 256, 256>>>(src, dst);
    k_p1norm<<<1, 128>>>(p1_w);

    // block 1: SAGE -> TopK(0.8) -> gap  (score fused in GEMM epilogue)
    k_aggmean<<<NBn / 4, 256>>>(5, x, 0);
    k_gemm<<<NBn / 64, 256>>>(0, nullptr, c1_wl, 5, x, c1_wr, c1_bl, 1, 8, 1,
                              nullptr, nullptr, p1_w, nullptr, 1);
    k_pool<<<Bg, 512>>>(1, KK1, 0);

    // block 2: SAGE -> SAGPool(0.5) -> gap  (t/r fused in GEMM epilogue)
    k_aggmean<<<NBn / 4, 256>>>(1, nullptr, 1);
    k_gemm<<<NBn / 64, 256>>>(0, nullptr, c2_wl, 1, nullptr, c2_wr, c2_bl, 2, 8, 1,
                              nullptr, nullptr, p2_wrel, p2_wroot, 2);
    k_gconv<<<NBn * 32 / 256, 256>>>(p2_brel);
    k_pool<<<Bg, 512>>>(2, KK2, 1);

    // block 3: GAT -> SAGPool(0.5) -> gap  (als/ald fused in GEMM, t/r fused in GAT)
    k_gemm<<<NBn / 64, 256>>>(2, nullptr, g_w, 0, nullptr, g_w, nullptr, 3, 4, 0,
                              g_as, g_ad, nullptr, nullptr, 0);
    k_vmat<<<1, 32>>>(g_we, g_ae);
    k_ale<<<NE / 256, 256>>>(ea);
    k_easum<<<256, 256>>>(ea, src, dst);
    k_alse<<<1, 32>>>();
    k_gat<<<NBn * 32 / 256, 256>>>(g_b, p3_wrel, p3_wroot);
    k_gconv<<<NBn * 32 / 256, 256>>>(p3_brel);
    k_pool<<<Bg, 512>>>(4, KK3, 2);

    // head MLP
    k_head<<<Bg, 128>>>(l1_w, l1_b, l2_w, l2_b, l3_w, l3_b, out);
}

// round 13
// speedup vs baseline: 1.0044x; 1.0044x over previous
#include <cuda_runtime.h>
#include <math.h>
#include <stdint.h>

#define NBn 65536
#define NE  1048576
#define Bg  128
#define Nn  512
#define KK1 410
#define KK2 205
#define KK3 103
#define FD  128

// packed fp32x2 FMA: d = a*b + c on both halves (SASS FFMA2)
#define FMA_F32X2(d, a, b, c) \
    asm("fma.rn.f32x2 %0, %1, %2, %3;" : "=l"(d) : "l"(a), "l"(b), "l"(c))
#define PACK_F32X2(out, lo, hi) \
    asm("mov.b64 %0, {%1, %2};" : "=l"(out) : "f"(lo), "f"(hi))
#define UNPACK_F32X2(lo, hi, in) \
    asm("mov.b64 {%0, %1}, %2;" : "=f"(lo), "=f"(hi) : "l"(in))

// ---------------- device global scratch ----------------
__device__ float d_agg[NBn * FD];
__device__ float d_xa [NBn * FD];
__device__ float d_xb [NBn * FD];
__device__ float d_xs [NBn * FD];
__device__ float d_xc [NBn * FD];
__device__ float d_score[NBn];
__device__ float d_t[NBn];
__device__ float d_r[NBn];
__device__ unsigned char d_nmask[NBn];
__device__ int   d_hist[NBn];
__device__ int   d_rowptr[NBn + 1];
__device__ int   d_posA[NBn];
__device__ int   d_bsum[256];
__device__ int   d_bsumx[256];
__device__ int2  d_se[NE];
__device__ float d_als[NBn * 4];
__device__ float d_ald[NBn * 4];
__device__ float d_ale[(size_t)NE * 4];
__device__ float d_V[28];
__device__ float d_alse[4];
__device__ float d_easum[8];
__device__ float d_gap[3 * Bg * FD];
__device__ float d_p1norm;

__device__ __forceinline__ float* getbuf(int id, const float* ext) {
    switch (id) {
        case 0: return d_agg;
        case 1: return d_xa;
        case 2: return d_xb;
        case 3: return d_xs;
        case 4: return d_xc;
        default: return (float*)ext;
    }
}

// ---------------- small utility kernels ----------------
__global__ void k_zero_hist() {
    int i = blockIdx.x * blockDim.x + threadIdx.x;
    if (i < NBn) d_hist[i] = 0;
}
__global__ void k_init_mask() {
    int i = blockIdx.x * blockDim.x + threadIdx.x;
    if (i < NBn) d_nmask[i] = 1;
}

// ---------------- CSR build ----------------
__global__ void k_hist(const int* __restrict__ dst) {
    int e = blockIdx.x * blockDim.x + threadIdx.x;
    if (e < NE) atomicAdd(&d_hist[dst[e]], 1);
}

__global__ void k_bsum() {
    int t = threadIdx.x;
    int v = d_hist[blockIdx.x * 256 + t];
    int lane = t & 31, w = t >> 5;
#pragma unroll
    for (int o = 16; o; o >>= 1) v += __shfl_down_sync(0xffffffffu, v, o);
    __shared__ int ws[8];
    if (lane == 0) ws[w] = v;
    __syncthreads();
    if (t == 0) {
        int s = 0;
#pragma unroll
        for (int i = 0; i < 8; i++) s += ws[i];
        d_bsum[blockIdx.x] = s;
    }
}

__global__ void k_scanb() {
    int t = threadIdx.x;
    int v = d_bsum[t];
    int lane = t & 31, w = t >> 5;
    int x = v;
#pragma unroll
    for (int o = 1; o < 32; o <<= 1) {
        int y = __shfl_up_sync(0xffffffffu, x, o);
        if (lane >= o) x += y;
    }
    __shared__ int ws[8];
    if (lane == 31) ws[w] = x;
    __syncthreads();
    __shared__ int wx[8];
    if (t == 0) {
        int run = 0;
#pragma unroll
        for (int i = 0; i < 8; i++) { wx[i] = run; run += ws[i]; }
    }
    __syncthreads();
    d_bsumx[t] = wx[w] + x - v;
    if (t == 0) d_rowptr[NBn] = NE;
}

__global__ void k_scan2() {
    int t = threadIdx.x;
    int i = blockIdx.x * 256 + t;
    int v = d_hist[i];
    int lane = t & 31, w = t >> 5;
    int x = v;
#pragma unroll
    for (int o = 1; o < 32; o <<= 1) {
        int y = __shfl_up_sync(0xffffffffu, x, o);
        if (lane >= o) x += y;
    }
    __shared__ int ws[8];
    if (lane == 31) ws[w] = x;
    __syncthreads();
    __shared__ int wx[8];
    if (t == 0) {
        int run = 0;
#pragma unroll
        for (int j = 0; j < 8; j++) { wx[j] = run; run += ws[j]; }
    }
    __syncthreads();
    int excl = d_bsumx[blockIdx.x] + wx[w] + x - v;
    d_rowptr[i] = excl;
    d_posA[i]   = excl;
}

__global__ void k_scatter(const int* __restrict__ src, const int* __restrict__ dst) {
    int e = blockIdx.x * blockDim.x + threadIdx.x;
    if (e >= NE) return;
    int p = atomicAdd(&d_posA[dst[e]], 1);
    d_se[p] = make_int2(src[e], e);
}

// ---------------- SAGE mean aggregation ----------------
// warp per dst; lane-parallel edge staging: one coalesced d_se load covers 32
// edges, ballot for liveness, then 1 shfl + 1 LDG.128 per edge.
__global__ void k_aggmean(int xid, const float* __restrict__ xext, int use_mask) {
    int w = (blockIdx.x * blockDim.x + threadIdx.x) >> 5;
    int lane = threadIdx.x & 31;
    if (w >= NBn) return;
    const float* X = getbuf(xid, xext);
    float4 a = make_float4(0.f, 0.f, 0.f, 0.f);
    float cnt = 0.f;
    if (!use_mask || d_nmask[w]) {
        int b = d_rowptr[w], e = d_rowptr[w + 1];
        for (int base = b; base < e; base += 32) {
            int n = e - base;
            if (n > 32) n = 32;
            int s = 0;
            if (lane < n) s = d_se[base + lane].x;
            unsigned live;
            if (use_mask) {
                bool lv = (lane < n) && d_nmask[s];
                live = __ballot_sync(0xffffffffu, lv);
            } else {
                live = (n == 32) ? 0xffffffffu : ((1u << n) - 1u);
            }
            while (live) {
                int j = __ffs(live) - 1;
                live &= live - 1;
                int sj = __shfl_sync(0xffffffffu, s, j);
                float4 v = *(const float4*)(X + (size_t)sj * FD + lane * 4);
                a.x += v.x; a.y += v.y; a.z += v.z; a.w += v.w;
                cnt += 1.f;
            }
        }
    }
    float inv = 1.f / fmaxf(cnt, 1.f);
    a.x *= inv; a.y *= inv; a.z *= inv; a.w *= inv;
    *(float4*)(d_agg + (size_t)w * FD + lane * 4) = a;
}

// ---------------- GEMM with fused epilogues ----------------
// smode 0: none; 1: d_score = tanh(row.sw1 / p1norm); 2: d_t = row.sw1, d_r = row.sw2
// as_w/ad_w: per-head GAT attention dots (width-8 reduce)
__global__ __launch_bounds__(256) void k_gemm(
    int a0id, const float* __restrict__ a0ext, const float* __restrict__ W0,
    int a1id, const float* __restrict__ a1ext, const float* __restrict__ W1,
    const float* __restrict__ bias, int cid, int ktiles, int dorelu,
    const float* __restrict__ as_w, const float* __restrict__ ad_w,
    const float* __restrict__ sw1, const float* __restrict__ sw2, int smode)
{
    __shared__ float As_t[32][66];
    __shared__ float Bs[32][128];
    int tid = threadIdx.x;
    int m0 = blockIdx.x * 64;
    int cx = tid & 31, ry = tid >> 5;

    unsigned long long acc[4][4];
    {
        unsigned long long z;
        PACK_F32X2(z, 0.f, 0.f);
#pragma unroll
        for (int p = 0; p < 4; p++)
#pragma unroll
            for (int j = 0; j < 4; j++) acc[p][j] = z;
    }

    for (int kt = 0; kt < ktiles; kt++) {
        const float* A; const float* W; int kl;
        if (kt < 4) { A = getbuf(a0id, a0ext); W = W0; kl = kt * 32; }
        else        { A = getbuf(a1id, a1ext); W = W1; kl = (kt - 4) * 32; }
#pragma unroll
        for (int r = 0; r < 2; r++) {
            int id = tid + 256 * r;
            int m = id >> 3, k4 = id & 7;
            float4 v = *(const float4*)&A[(size_t)(m0 + m) * FD + kl + k4 * 4];
            As_t[k4 * 4 + 0][m] = v.x;
            As_t[k4 * 4 + 1][m] = v.y;
            As_t[k4 * 4 + 2][m] = v.z;
            As_t[k4 * 4 + 3][m] = v.w;
        }
#pragma unroll
        for (int r = 0; r < 4; r++) {
            int id = tid + 256 * r;          // 1024 float4s total
            int kk = id >> 5, n4 = id & 31;
            *(float4*)&Bs[kk][n4 * 4] =
                *(const float4*)&W[(size_t)(kl + kk) * FD + n4 * 4];
        }
        __syncthreads();
#pragma unroll
        for (int kk = 0; kk < 32; kk++) {
            float4 bv = *(const float4*)&Bs[kk][cx * 4];
            unsigned long long bb0, bb1, bb2, bb3;
            PACK_F32X2(bb0, bv.x, bv.x);
            PACK_F32X2(bb1, bv.y, bv.y);
            PACK_F32X2(bb2, bv.z, bv.z);
            PACK_F32X2(bb3, bv.w, bv.w);
#pragma unroll
            for (int p = 0; p < 4; p++) {
                unsigned long long aa =
                    *(const unsigned long long*)&As_t[kk][ry * 8 + 2 * p];
                FMA_F32X2(acc[p][0], aa, bb0, acc[p][0]);
                FMA_F32X2(acc[p][1], aa, bb1, acc[p][1]);
                FMA_F32X2(acc[p][2], aa, bb2, acc[p][2]);
                FMA_F32X2(acc[p][3], aa, bb3, acc[p][3]);
            }
        }
        __syncthreads();
    }
    int c0 = cx * 4;
    float b0 = 0.f, b1 = 0.f, b2 = 0.f, b3 = 0.f;
    if (bias) { b0 = bias[c0]; b1 = bias[c0 + 1]; b2 = bias[c0 + 2]; b3 = bias[c0 + 3]; }
    float aw0 = 0.f, aw1 = 0.f, aw2 = 0.f, aw3 = 0.f, dw0 = 0.f, dw1 = 0.f, dw2 = 0.f, dw3 = 0.f;
    if (as_w) {
        aw0 = as_w[c0]; aw1 = as_w[c0 + 1]; aw2 = as_w[c0 + 2]; aw3 = as_w[c0 + 3];
        dw0 = ad_w[c0]; dw1 = ad_w[c0 + 1]; dw2 = ad_w[c0 + 2]; dw3 = ad_w[c0 + 3];
    }
    float s10 = 0.f, s11 = 0.f, s12 = 0.f, s13 = 0.f, s20 = 0.f, s21 = 0.f, s22 = 0.f, s23 = 0.f;
    if (smode) {
        s10 = sw1[c0]; s11 = sw1[c0 + 1]; s12 = sw1[c0 + 2]; s13 = sw1[c0 + 3];
        if (smode == 2) { s20 = sw2[c0]; s21 = sw2[c0 + 1]; s22 = sw2[c0 + 2]; s23 = sw2[c0 + 3]; }
    }
    int h = cx >> 3;
    float* C = getbuf(cid, nullptr);
#pragma unroll
    for (int p = 0; p < 4; p++) {
        size_t me = m0 + ry * 8 + 2 * p;
        float4 oe, oo;
        UNPACK_F32X2(oe.x, oo.x, acc[p][0]);
        UNPACK_F32X2(oe.y, oo.y, acc[p][1]);
        UNPACK_F32X2(oe.z, oo.z, acc[p][2]);
        UNPACK_F32X2(oe.w, oo.w, acc[p][3]);
        oe.x += b0; oe.y += b1; oe.z += b2; oe.w += b3;
        oo.x += b0; oo.y += b1; oo.z += b2; oo.w += b3;
        if (dorelu) {
            oe.x = fmaxf(oe.x, 0.f); oe.y = fmaxf(oe.y, 0.f);
            oe.z = fmaxf(oe.z, 0.f); oe.w = fmaxf(oe.w, 0.f);
            oo.x = fmaxf(oo.x, 0.f); oo.y = fmaxf(oo.y, 0.f);
            oo.z = fmaxf(oo.z, 0.f); oo.w = fmaxf(oo.w, 0.f);
        }
        *(float4*)&C[me * FD + c0] = oe;
        *(float4*)&C[(me + 1) * FD + c0] = oo;
        if (as_w) {
            float pae = oe.x * aw0 + oe.y * aw1 + oe.z * aw2 + oe.w * aw3;
            float pao = oo.x * aw0 + oo.y * aw1 + oo.z * aw2 + oo.w * aw3;
            float pde = oe.x * dw0 + oe.y * dw1 + oe.z * dw2 + oe.w * dw3;
            float pdo = oo.x * dw0 + oo.y * dw1 + oo.z * dw2 + oo.w * dw3;
#pragma unroll
            for (int o = 4; o; o >>= 1) {
                pae += __shfl_down_sync(0xffffffffu, pae, o, 8);
                pao += __shfl_down_sync(0xffffffffu, pao, o, 8);
                pde += __shfl_down_sync(0xffffffffu, pde, o, 8);
                pdo += __shfl_down_sync(0xffffffffu, pdo, o, 8);
            }
            if ((cx & 7) == 0) {
                d_als[me * 4 + h] = pae;
                d_als[(me + 1) * 4 + h] = pao;
                d_ald[me * 4 + h] = pde;
                d_ald[(me + 1) * 4 + h] = pdo;
            }
        }
        if (smode) {
            float p1e = oe.x * s10 + oe.y * s11 + oe.z * s12 + oe.w * s13;
            float p1o = oo.x * s10 + oo.y * s11 + oo.z * s12 + oo.w * s13;
            float p2e = oe.x * s20 + oe.y * s21 + oe.z * s22 + oe.w * s23;
            float p2o = oo.x * s20 + oo.y * s21 + oo.z * s22 + oo.w * s23;
#pragma unroll
            for (int o = 16; o; o >>= 1) {
                p1e += __shfl_down_sync(0xffffffffu, p1e, o);
                p1o += __shfl_down_sync(0xffffffffu, p1o, o);
                p2e += __shfl_down_sync(0xffffffffu, p2e, o);
                p2o += __shfl_down_sync(0xffffffffu, p2o, o);
            }
            if (cx == 0) {
                if (smode == 1) {
                    float inv = 1.f / d_p1norm;
                    d_score[me] = tanhf(p1e * inv);
                    d_score[me + 1] = tanhf(p1o * inv);
                } else {
                    d_t[me] = p1e; d_t[me + 1] = p1o;
                    d_r[me] = p2e; d_r[me + 1] = p2o;
                }
            }
        }
    }
}

__global__ void k_p1norm(const float* __restrict__ w) {  // <<<1,128>>>
    __shared__ float sm[128];
    int t = threadIdx.x;
    float v = w[t];
    sm[t] = v * v;
    __syncthreads();
    for (int o = 64; o; o >>= 1) { if (t < o) sm[t] += sm[t + o]; __syncthreads(); }
    if (t == 0) d_p1norm = sqrtf(sm[0]);
}

// GraphConv score: tanh( sum_{live e->d} t[src] + brel + r[d] )
__global__ void k_gconv(const float* __restrict__ brel) {
    int d = (blockIdx.x * blockDim.x + threadIdx.x) >> 5;
    int lane = threadIdx.x & 31;
    if (d >= NBn) return;
    float a = 0.f;
    if (d_nmask[d]) {
        int b = d_rowptr[d], e = d_rowptr[d + 1];
        for (int i = b + lane; i < e; i += 32) {
            int s = d_se[i].x;
            if (d_nmask[s]) a += d_t[s];
        }
    }
#pragma unroll
    for (int o = 16; o; o >>= 1) a += __shfl_down_sync(0xffffffffu, a, o);
    if (lane == 0) d_score[d] = tanhf(a + brel[0] + d_r[d]);
}

// ---------------- top-k pool (block per graph, 512 threads) ----------------
__global__ __launch_bounds__(512) void k_pool(int xid, int K, int stage) {
    int g = blockIdx.x;
    int t = threadIdx.x;
    int tx = t & 127, ty = t >> 7;
    __shared__ float s[Nn];
    __shared__ unsigned char sel[Nn];
    {
        int n = g * Nn + t;
        s[t] = d_nmask[n] ? d_score[n] : -INFINITY;
    }
    __syncthreads();
    {
        float si = s[t];
        int rank = 0;
        for (int j = 0; j < Nn; j++) {
            float sj = s[j];
            rank += (sj > si) || ((sj == si) && (j < t));
        }
        int se = (rank < K) ? 1 : 0;
        sel[t] = (unsigned char)se;
        d_nmask[g * Nn + t] = (unsigned char)se;
    }
    __syncthreads();
    float* X = getbuf(xid, nullptr);
    float acc = 0.f;
    for (int n = ty; n < Nn; n += 4) {
        size_t idx = (size_t)(g * Nn + n) * FD + tx;
        float v = sel[n] ? X[idx] * s[n] : 0.f;
        X[idx] = v;
        acc += v;
    }
    __shared__ float gs[4][128];
    gs[ty][tx] = acc;
    __syncthreads();
    if (ty == 0)
        d_gap[stage * Bg * FD + g * FD + tx] =
            (gs[0][tx] + gs[1][tx] + gs[2][tx] + gs[3][tx]) / (float)K;
}

// ---------------- GAT ----------------
__global__ void k_vmat(const float* __restrict__ gwe, const float* __restrict__ gae) {  // <<<1,32>>>
    int lane = threadIdx.x;
    if (lane < 8) d_easum[lane] = 0.f;
    for (int o = 0; o < 28; o++) {
        int ed = o >> 2, h = o & 3;
        float p = gwe[ed * FD + h * 32 + lane] * gae[h * 32 + lane];
#pragma unroll
        for (int off = 16; off; off >>= 1) p += __shfl_down_sync(0xffffffffu, p, off);
        if (lane == 0) d_V[ed * 4 + h] = p;
    }
}
__global__ void k_ale(const float* __restrict__ ea) {
    int e = blockIdx.x * blockDim.x + threadIdx.x;
    if (e >= NE) return;
    float at[7];
#pragma unroll
    for (int ed = 0; ed < 7; ed++) at[ed] = ea[(size_t)e * 7 + ed];
#pragma unroll
    for (int h = 0; h < 4; h++) {
        float a = 0.f;
#pragma unroll
        for (int ed = 0; ed < 7; ed++) a += at[ed] * d_V[ed * 4 + h];
        d_ale[(size_t)e * 4 + h] = a;
    }
}
__global__ void k_easum(const float* __restrict__ ea, const int* __restrict__ src,
                        const int* __restrict__ dst) {
    float loc[8];
#pragma unroll
    for (int k = 0; k < 8; k++) loc[k] = 0.f;
    for (int e = blockIdx.x * blockDim.x + threadIdx.x; e < NE; e += gridDim.x * blockDim.x) {
        if (d_nmask[src[e]] && d_nmask[dst[e]]) {
#pragma unroll
            for (int ed = 0; ed < 7; ed++) loc[ed] += ea[(size_t)e * 7 + ed];
            loc[7] += 1.f;
        }
    }
    int lane = threadIdx.x & 31;
#pragma unroll
    for (int k = 0; k < 8; k++) {
        float v = loc[k];
#pragma unroll
        for (int o = 16; o; o >>= 1) v += __shfl_down_sync(0xffffffffu, v, o);
        if (lane == 0) atomicAdd(&d_easum[k], v);
    }
}
__global__ void k_alse() {  // <<<1,32>>>
    int lane = threadIdx.x;
    if (lane < 4) {
        float c = fmaxf(d_easum[7], 1.f);
        float a = 0.f;
#pragma unroll
        for (int ed = 0; ed < 7; ed++) a += (d_easum[ed] / c) * d_V[ed * 4 + lane];
        d_alse[lane] = a;
    }
}

// warp per dst; online softmax; each lane owns 4 columns of head (lane>>3);
// fused p3 score dots (d_t, d_r) in the epilogue
__global__ void k_gat(const float* __restrict__ gb,
                      const float* __restrict__ w1, const float* __restrict__ w2) {
    int d = (blockIdx.x * blockDim.x + threadIdx.x) >> 5;
    int lane = threadIdx.x & 31;
    if (d >= NBn) return;
    int h = lane >> 3;
    float m = -INFINITY, den = 0.f;
    float4 acc = make_float4(0.f, 0.f, 0.f, 0.f);
    bool dal = d_nmask[d] != 0;
    float aldL = (lane < 4) ? d_ald[d * 4 + lane] : 0.f;
    if (dal) {
        int b = d_rowptr[d], e2 = d_rowptr[d + 1];
        for (int i = b; i < e2; i++) {
            int2 se = d_se[i];
            int s = se.x;
            if (!d_nmask[s]) continue;
            int e = se.y;
            float tl = 0.f;
            if (lane < 4) {
                tl = d_als[s * 4 + lane] + aldL + d_ale[(size_t)e * 4 + lane];
                tl = tl > 0.f ? tl : 0.2f * tl;
            }
            float aj = __shfl_sync(0xffffffffu, tl, h);
            float4 xv = *(const float4*)(d_xs + (size_t)s * FD + lane * 4);
            if (aj > m) {
                float sc = __expf(m - aj);
                den = den * sc + 1.f;
                acc.x = acc.x * sc + xv.x;
                acc.y = acc.y * sc + xv.y;
                acc.z = acc.z * sc + xv.z;
                acc.w = acc.w * sc + xv.w;
                m = aj;
            } else {
                float c = __expf(aj - m);
                den += c;
                acc.x += c * xv.x;
                acc.y += c * xv.y;
                acc.z += c * xv.z;
                acc.w += c * xv.w;
            }
        }
        // self loop
        float tl = 0.f;
        if (lane < 4) {
            tl = d_als[d * 4 + lane] + aldL + d_alse[lane];
            tl = tl > 0.f ? tl : 0.2f * tl;
        }
        float aj = __shfl_sync(0xffffffffu, tl, h);
        float4 xv = *(const float4*)(d_xs + (size_t)d * FD + lane * 4);
        if (aj > m) {
            float sc = __expf(m - aj);
            den = den * sc + 1.f;
            acc.x = acc.x * sc + xv.x;
            acc.y = acc.y * sc + xv.y;
            acc.z = acc.z * sc + xv.z;
            acc.w = acc.w * sc + xv.w;
            m = aj;
        } else {
            float c = __expf(aj - m);
            den += c;
            acc.x += c * xv.x;
            acc.y += c * xv.y;
            acc.z += c * xv.z;
            acc.w += c * xv.w;
        }
    }
    float invd = 1.f / fmaxf(den, 1e-16f);
    float4 bb = *(const float4*)(gb + lane * 4);
    float4 o;
    o.x = fmaxf(acc.x * invd + bb.x, 0.f);
    o.y = fmaxf(acc.y * invd + bb.y, 0.f);
    o.z = fmaxf(acc.z * invd + bb.z, 0.f);
    o.w = fmaxf(acc.w * invd + bb.w, 0.f);
    *(float4*)(d_xc + (size_t)d * FD + lane * 4) = o;
    // fused p3 score dots
    float4 wv1 = *(const float4*)(w1 + lane * 4);
    float4 wv2 = *(const float4*)(w2 + lane * 4);
    float p1 = o.x * wv1.x + o.y * wv1.y + o.z * wv1.z + o.w * wv1.w;
    float p2 = o.x * wv2.x + o.y * wv2.y + o.z * wv2.z + o.w * wv2.w;
#pragma unroll
    for (int off = 16; off; off >>= 1) {
        p1 += __shfl_down_sync(0xffffffffu, p1, off);
        p2 += __shfl_down_sync(0xffffffffu, p2, off);
    }
    if (lane == 0) { d_t[d] = p1; d_r[d] = p2; }
}

// ---------------- head MLP (block per graph) ----------------
__global__ void k_head(const float* __restrict__ l1w, const float* __restrict__ l1b,
                       const float* __restrict__ l2w, const float* __restrict__ l2b,
                       const float* __restrict__ l3w, const float* __restrict__ l3b,
                       float* __restrict__ out) {
    int g = blockIdx.x;
    int t = threadIdx.x;
    __shared__ float h[128], h2[128], h3[64];
    h[t] = d_gap[g * FD + t] + d_gap[Bg * FD + g * FD + t] + d_gap[2 * Bg * FD + g * FD + t];
    __syncthreads();
    float a = l1b[t];
    for (int k = 0; k < 128; k++) a += h[k] * l1w[k * 128 + t];
    h2[t] = fmaxf(a, 0.f);
    __syncthreads();
    if (t < 64) {
        float a2 = l2b[t];
        for (int k = 0; k < 128; k++) a2 += h2[k] * l2w[k * 64 + t];
        h3[t] = fmaxf(a2, 0.f);
    }
    __syncthreads();
    if (t == 0) {
        float z = l3b[0];
        for (int k = 0; k < 64; k++) z += h3[k] * l3w[k];
        out[g] = 1.f / (1.f + expf(-z));
    }
}

// ---------------- launch ----------------
extern "C" void kernel_launch(void* const* d_in, const int* in_sizes, int n_in,
                              void* d_out, int out_size) {
    const float* x      = (const float*)d_in[0];
    const int*   ei     = (const int*)d_in[1];
    const float* ea     = (const float*)d_in[2];
    const float* c1_wl  = (const float*)d_in[3];
    const float* c1_bl  = (const float*)d_in[4];
    const float* c1_wr  = (const float*)d_in[5];
    const float* p1_w   = (const float*)d_in[6];
    const float* c2_wl  = (const float*)d_in[7];
    const float* c2_bl  = (const float*)d_in[8];
    const float* c2_wr  = (const float*)d_in[9];
    const float* p2_wrel= (const float*)d_in[10];
    const float* p2_brel= (const float*)d_in[11];
    const float* p2_wroot=(const float*)d_in[12];
    const float* g_w    = (const float*)d_in[13];
    const float* g_as   = (const float*)d_in[14];
    const float* g_ad   = (const float*)d_in[15];
    const float* g_we   = (const float*)d_in[16];
    const float* g_ae   = (const float*)d_in[17];
    const float* g_b    = (const float*)d_in[18];
    const float* p3_wrel= (const float*)d_in[19];
    const float* p3_brel= (const float*)d_in[20];
    const float* p3_wroot=(const float*)d_in[21];
    const float* l1_w   = (const float*)d_in[22];
    const float* l1_b   = (const float*)d_in[23];
    const float* l2_w   = (const float*)d_in[24];
    const float* l2_b   = (const float*)d_in[25];
    const float* l3_w   = (const float*)d_in[26];
    const float* l3_b   = (const float*)d_in[27];
    const int* src = ei;
    const int* dst = ei + NE;
    float* out = (float*)d_out;

    // CSR build (parallel 3-phase scan)
    k_zero_hist<<<NBn / 256, 256>>>();
    k_init_mask<<<NBn / 256, 256>>>();
    k_hist<<<NE / 256, 256>>>(dst);
    k_bsum<<<256, 256>>>();
    k_scanb<<<1, 256>>>();
    k_scan2<<<256, 256>>>();
    k_scatter<<<NE / 256, 256>>>(src, dst);
    k_p1norm<<<1, 128>>>(p1_w);

    // block 1: SAGE -> TopK(0.8) -> gap  (score fused in GEMM epilogue)
    k_aggmean<<<NBn / 8, 256>>>(5, x, 0);
    k_gemm<<<NBn / 64, 256>>>(0, nullptr, c1_wl, 5, x, c1_wr, c1_bl, 1, 8, 1,
                              nullptr, nullptr, p1_w, nullptr, 1);
    k_pool<<<Bg, 512>>>(1, KK1, 0);

    // block 2: SAGE -> SAGPool(0.5) -> gap  (t/r fused in GEMM epilogue)
    k_aggmean<<<NBn / 8, 256>>>(1, nullptr, 1);
    k_gemm<<<NBn / 64, 256>>>(0, nullptr, c2_wl, 1, nullptr, c2_wr, c2_bl, 2, 8, 1,
                              nullptr, nullptr, p2_wrel, p2_wroot, 2);
    k_gconv<<<NBn * 32 / 256, 256>>>(p2_brel);
    k_pool<<<Bg, 512>>>(2, KK2, 1);

    // block 3: GAT -> SAGPool(0.5) -> gap  (als/ald fused in GEMM, t/r fused in GAT)
    k_gemm<<<NBn / 64, 256>>>(2, nullptr, g_w, 0, nullptr, g_w, nullptr, 3, 4, 0,
                              g_as, g_ad, nullptr, nullptr, 0);
    k_vmat<<<1, 32>>>(g_we, g_ae);
    k_ale<<<NE / 256, 256>>>(ea);
    k_easum<<<256, 256>>>(ea, src, dst);
    k_alse<<<1, 32>>>();
    k_gat<<<NBn * 32 / 256, 256>>>(g_b, p3_wrel, p3_wroot);
    k_gconv<<<NBn * 32 / 256, 256>>>(p3_brel);
    k_pool<<<Bg, 512>>>(4, KK3, 2);

    // head MLP
    k_head<<<Bg, 128>>>(l1_w, l1_b, l2_w, l2_b, l3_w, l3_b, out);
}

// round 14
// speedup vs baseline: 1.0320x; 1.0276x over previous
#include <cuda_runtime.h>
#include <math.h>
#include <stdint.h>

#define NBn 65536
#define NE  1048576
#define Bg  128
#define Nn  512
#define KK1 410
#define KK2 205
#define KK3 103
#define FD  128

// packed fp32x2 FMA: d = a*b + c on both halves (SASS FFMA2)
#define FMA_F32X2(d, a, b, c) \
    asm("fma.rn.f32x2 %0, %1, %2, %3;" : "=l"(d) : "l"(a), "l"(b), "l"(c))
#define PACK_F32X2(out, lo, hi) \
    asm("mov.b64 %0, {%1, %2};" : "=l"(out) : "f"(lo), "f"(hi))
#define UNPACK_F32X2(lo, hi, in) \
    asm("mov.b64 {%0, %1}, %2;" : "=f"(lo), "=f"(hi) : "l"(in))

// ---------------- device global scratch ----------------
__device__ float d_agg[NBn * FD];
__device__ float d_xa [NBn * FD];
__device__ float d_xb [NBn * FD];
__device__ float d_xs [NBn * FD];
__device__ float d_xc [NBn * FD];
__device__ float d_score[NBn];
__device__ float d_t[NBn];
__device__ float d_r[NBn];
__device__ unsigned char d_nmask[NBn];
__device__ int   d_hist[NBn];
__device__ int   d_rowptr[NBn + 1];
__device__ int   d_posA[NBn];
__device__ int   d_bsum[256];
__device__ int   d_bsumx[256];
__device__ int2  d_se[NE];
__device__ float d_als[NBn * 4];
__device__ float d_ald[NBn * 4];
__device__ float d_ale[(size_t)NE * 4];
__device__ float d_V[28];
__device__ float d_alse[4];
__device__ float d_easum[8];
__device__ float d_gap[3 * Bg * FD];
__device__ float d_p1norm;

__device__ __forceinline__ float* getbuf(int id, const float* ext) {
    switch (id) {
        case 0: return d_agg;
        case 1: return d_xa;
        case 2: return d_xb;
        case 3: return d_xs;
        case 4: return d_xc;
        default: return (float*)ext;
    }
}

// ---------------- init: hist=0, nmask=1 (merged) ----------------
__global__ void k_init() {
    int i = blockIdx.x * blockDim.x + threadIdx.x;
    if (i < NBn) { d_hist[i] = 0; d_nmask[i] = 1; }
}

// ---------------- CSR build ----------------
__global__ void k_hist(const int* __restrict__ dst) {
    int e = blockIdx.x * blockDim.x + threadIdx.x;
    if (e < NE) atomicAdd(&d_hist[dst[e]], 1);
}

__global__ void k_bsum() {
    int t = threadIdx.x;
    int v = d_hist[blockIdx.x * 256 + t];
    int lane = t & 31, w = t >> 5;
#pragma unroll
    for (int o = 16; o; o >>= 1) v += __shfl_down_sync(0xffffffffu, v, o);
    __shared__ int ws[8];
    if (lane == 0) ws[w] = v;
    __syncthreads();
    if (t == 0) {
        int s = 0;
#pragma unroll
        for (int i = 0; i < 8; i++) s += ws[i];
        d_bsum[blockIdx.x] = s;
    }
}

__global__ void k_scanb() {
    int t = threadIdx.x;
    int v = d_bsum[t];
    int lane = t & 31, w = t >> 5;
    int x = v;
#pragma unroll
    for (int o = 1; o < 32; o <<= 1) {
        int y = __shfl_up_sync(0xffffffffu, x, o);
        if (lane >= o) x += y;
    }
    __shared__ int ws[8];
    if (lane == 31) ws[w] = x;
    __syncthreads();
    __shared__ int wx[8];
    if (t == 0) {
        int run = 0;
#pragma unroll
        for (int i = 0; i < 8; i++) { wx[i] = run; run += ws[i]; }
    }
    __syncthreads();
    d_bsumx[t] = wx[w] + x - v;
    if (t == 0) d_rowptr[NBn] = NE;
}

__global__ void k_scan2() {
    int t = threadIdx.x;
    int i = blockIdx.x * 256 + t;
    int v = d_hist[i];
    int lane = t & 31, w = t >> 5;
    int x = v;
#pragma unroll
    for (int o = 1; o < 32; o <<= 1) {
        int y = __shfl_up_sync(0xffffffffu, x, o);
        if (lane >= o) x += y;
    }
    __shared__ int ws[8];
    if (lane == 31) ws[w] = x;
    __syncthreads();
    __shared__ int wx[8];
    if (t == 0) {
        int run = 0;
#pragma unroll
        for (int j = 0; j < 8; j++) { wx[j] = run; run += ws[j]; }
    }
    __syncthreads();
    int excl = d_bsumx[blockIdx.x] + wx[w] + x - v;
    d_rowptr[i] = excl;
    d_posA[i]   = excl;
}

__global__ void k_scatter(const int* __restrict__ src, const int* __restrict__ dst) {
    int e = blockIdx.x * blockDim.x + threadIdx.x;
    if (e >= NE) return;
    int p = atomicAdd(&d_posA[dst[e]], 1);
    d_se[p] = make_int2(src[e], e);
}

// ---------------- SAGE mean aggregation (warp per dst, unroll-2 float4) ----------------
__global__ void k_aggmean(int xid, const float* __restrict__ xext, int use_mask) {
    int w = (blockIdx.x * blockDim.x + threadIdx.x) >> 5;
    int lane = threadIdx.x & 31;
    if (w >= NBn) return;
    const float* X = getbuf(xid, xext);
    float4 a = make_float4(0.f, 0.f, 0.f, 0.f);
    float cnt = 0.f;
    if (!use_mask || d_nmask[w]) {
        int b = d_rowptr[w], e = d_rowptr[w + 1];
        int i = b;
        for (; i + 1 < e; i += 2) {
            int s0 = d_se[i].x, s1 = d_se[i + 1].x;
            bool l0 = !use_mask || d_nmask[s0];
            bool l1 = !use_mask || d_nmask[s1];
            float4 v0, v1;
            if (l0) v0 = *(const float4*)(X + (size_t)s0 * FD + lane * 4);
            if (l1) v1 = *(const float4*)(X + (size_t)s1 * FD + lane * 4);
            if (l0) { a.x += v0.x; a.y += v0.y; a.z += v0.z; a.w += v0.w; cnt += 1.f; }
            if (l1) { a.x += v1.x; a.y += v1.y; a.z += v1.z; a.w += v1.w; cnt += 1.f; }
        }
        if (i < e) {
            int s0 = d_se[i].x;
            if (!use_mask || d_nmask[s0]) {
                float4 v0 = *(const float4*)(X + (size_t)s0 * FD + lane * 4);
                a.x += v0.x; a.y += v0.y; a.z += v0.z; a.w += v0.w; cnt += 1.f;
            }
        }
    }
    float inv = 1.f / fmaxf(cnt, 1.f);
    a.x *= inv; a.y *= inv; a.z *= inv; a.w *= inv;
    *(float4*)(d_agg + (size_t)w * FD + lane * 4) = a;
}

// ---------------- GEMM with fused epilogues (R11-exact) ----------------
__global__ __launch_bounds__(256) void k_gemm(
    int a0id, const float* __restrict__ a0ext, const float* __restrict__ W0,
    int a1id, const float* __restrict__ a1ext, const float* __restrict__ W1,
    const float* __restrict__ bias, int cid, int ktiles, int dorelu,
    const float* __restrict__ as_w, const float* __restrict__ ad_w,
    const float* __restrict__ sw1, const float* __restrict__ sw2, int smode)
{
    __shared__ float As_t[32][66];
    __shared__ float Bs[32][128];
    int tid = threadIdx.x;
    int m0 = blockIdx.x * 64;
    int cx = tid & 31, ry = tid >> 5;

    unsigned long long acc[4][4];
    {
        unsigned long long z;
        PACK_F32X2(z, 0.f, 0.f);
#pragma unroll
        for (int p = 0; p < 4; p++)
#pragma unroll
            for (int j = 0; j < 4; j++) acc[p][j] = z;
    }

    for (int kt = 0; kt < ktiles; kt++) {
        const float* A; const float* W; int kl;
        if (kt < 4) { A = getbuf(a0id, a0ext); W = W0; kl = kt * 32; }
        else        { A = getbuf(a1id, a1ext); W = W1; kl = (kt - 4) * 32; }
#pragma unroll
        for (int r = 0; r < 2; r++) {
            int id = tid + 256 * r;
            int m = id >> 3, k4 = id & 7;
            float4 v = *(const float4*)&A[(size_t)(m0 + m) * FD + kl + k4 * 4];
            As_t[k4 * 4 + 0][m] = v.x;
            As_t[k4 * 4 + 1][m] = v.y;
            As_t[k4 * 4 + 2][m] = v.z;
            As_t[k4 * 4 + 3][m] = v.w;
        }
#pragma unroll
        for (int r = 0; r < 16; r++) {
            int id = tid + 256 * r;
            int kk = id >> 7, n = id & 127;
            Bs[kk][n] = W[(size_t)(kl + kk) * FD + n];
        }
        __syncthreads();
#pragma unroll
        for (int kk = 0; kk < 32; kk++) {
            float4 bv = *(const float4*)&Bs[kk][cx * 4];
            unsigned long long bb0, bb1, bb2, bb3;
            PACK_F32X2(bb0, bv.x, bv.x);
            PACK_F32X2(bb1, bv.y, bv.y);
            PACK_F32X2(bb2, bv.z, bv.z);
            PACK_F32X2(bb3, bv.w, bv.w);
#pragma unroll
            for (int p = 0; p < 4; p++) {
                unsigned long long aa =
                    *(const unsigned long long*)&As_t[kk][ry * 8 + 2 * p];
                FMA_F32X2(acc[p][0], aa, bb0, acc[p][0]);
                FMA_F32X2(acc[p][1], aa, bb1, acc[p][1]);
                FMA_F32X2(acc[p][2], aa, bb2, acc[p][2]);
                FMA_F32X2(acc[p][3], aa, bb3, acc[p][3]);
            }
        }
        __syncthreads();
    }
    int c0 = cx * 4;
    float b0 = 0.f, b1 = 0.f, b2 = 0.f, b3 = 0.f;
    if (bias) { b0 = bias[c0]; b1 = bias[c0 + 1]; b2 = bias[c0 + 2]; b3 = bias[c0 + 3]; }
    float aw0 = 0.f, aw1 = 0.f, aw2 = 0.f, aw3 = 0.f, dw0 = 0.f, dw1 = 0.f, dw2 = 0.f, dw3 = 0.f;
    if (as_w) {
        aw0 = as_w[c0]; aw1 = as_w[c0 + 1]; aw2 = as_w[c0 + 2]; aw3 = as_w[c0 + 3];
        dw0 = ad_w[c0]; dw1 = ad_w[c0 + 1]; dw2 = ad_w[c0 + 2]; dw3 = ad_w[c0 + 3];
    }
    float s10 = 0.f, s11 = 0.f, s12 = 0.f, s13 = 0.f, s20 = 0.f, s21 = 0.f, s22 = 0.f, s23 = 0.f;
    if (smode) {
        s10 = sw1[c0]; s11 = sw1[c0 + 1]; s12 = sw1[c0 + 2]; s13 = sw1[c0 + 3];
        if (smode == 2) { s20 = sw2[c0]; s21 = sw2[c0 + 1]; s22 = sw2[c0 + 2]; s23 = sw2[c0 + 3]; }
    }
    int h = cx >> 3;
    float* C = getbuf(cid, nullptr);
#pragma unroll
    for (int p = 0; p < 4; p++) {
        size_t me = m0 + ry * 8 + 2 * p;
        float4 oe, oo;
        UNPACK_F32X2(oe.x, oo.x, acc[p][0]);
        UNPACK_F32X2(oe.y, oo.y, acc[p][1]);
        UNPACK_F32X2(oe.z, oo.z, acc[p][2]);
        UNPACK_F32X2(oe.w, oo.w, acc[p][3]);
        oe.x += b0; oe.y += b1; oe.z += b2; oe.w += b3;
        oo.x += b0; oo.y += b1; oo.z += b2; oo.w += b3;
        if (dorelu) {
            oe.x = fmaxf(oe.x, 0.f); oe.y = fmaxf(oe.y, 0.f);
            oe.z = fmaxf(oe.z, 0.f); oe.w = fmaxf(oe.w, 0.f);
            oo.x = fmaxf(oo.x, 0.f); oo.y = fmaxf(oo.y, 0.f);
            oo.z = fmaxf(oo.z, 0.f); oo.w = fmaxf(oo.w, 0.f);
        }
        *(float4*)&C[me * FD + c0] = oe;
        *(float4*)&C[(me + 1) * FD + c0] = oo;
        if (as_w) {
            float pae = oe.x * aw0 + oe.y * aw1 + oe.z * aw2 + oe.w * aw3;
            float pao = oo.x * aw0 + oo.y * aw1 + oo.z * aw2 + oo.w * aw3;
            float pde = oe.x * dw0 + oe.y * dw1 + oe.z * dw2 + oe.w * dw3;
            float pdo = oo.x * dw0 + oo.y * dw1 + oo.z * dw2 + oo.w * dw3;
#pragma unroll
            for (int o = 4; o; o >>= 1) {
                pae += __shfl_down_sync(0xffffffffu, pae, o, 8);
                pao += __shfl_down_sync(0xffffffffu, pao, o, 8);
                pde += __shfl_down_sync(0xffffffffu, pde, o, 8);
                pdo += __shfl_down_sync(0xffffffffu, pdo, o, 8);
            }
            if ((cx & 7) == 0) {
                d_als[me * 4 + h] = pae;
                d_als[(me + 1) * 4 + h] = pao;
                d_ald[me * 4 + h] = pde;
                d_ald[(me + 1) * 4 + h] = pdo;
            }
        }
        if (smode) {
            float p1e = oe.x * s10 + oe.y * s11 + oe.z * s12 + oe.w * s13;
            float p1o = oo.x * s10 + oo.y * s11 + oo.z * s12 + oo.w * s13;
            float p2e = oe.x * s20 + oe.y * s21 + oe.z * s22 + oe.w * s23;
            float p2o = oo.x * s20 + oo.y * s21 + oo.z * s22 + oo.w * s23;
#pragma unroll
            for (int o = 16; o; o >>= 1) {
                p1e += __shfl_down_sync(0xffffffffu, p1e, o);
                p1o += __shfl_down_sync(0xffffffffu, p1o, o);
                p2e += __shfl_down_sync(0xffffffffu, p2e, o);
                p2o += __shfl_down_sync(0xffffffffu, p2o, o);
            }
            if (cx == 0) {
                if (smode == 1) {
                    float inv = 1.f / d_p1norm;
                    d_score[me] = tanhf(p1e * inv);
                    d_score[me + 1] = tanhf(p1o * inv);
                } else {
                    d_t[me] = p1e; d_t[me + 1] = p1o;
                    d_r[me] = p2e; d_r[me + 1] = p2o;
                }
            }
        }
    }
}

__global__ void k_p1norm(const float* __restrict__ w) {  // <<<1,128>>>
    __shared__ float sm[128];
    int t = threadIdx.x;
    float v = w[t];
    sm[t] = v * v;
    __syncthreads();
    for (int o = 64; o; o >>= 1) { if (t < o) sm[t] += sm[t + o]; __syncthreads(); }
    if (t == 0) d_p1norm = sqrtf(sm[0]);
}

// GraphConv score: tanh( sum_{live e->d} t[src] + brel + r[d] )
__global__ void k_gconv(const float* __restrict__ brel) {
    int d = (blockIdx.x * blockDim.x + threadIdx.x) >> 5;
    int lane = threadIdx.x & 31;
    if (d >= NBn) return;
    float a = 0.f;
    if (d_nmask[d]) {
        int b = d_rowptr[d], e = d_rowptr[d + 1];
        for (int i = b + lane; i < e; i += 32) {
            int s = d_se[i].x;
            if (d_nmask[s]) a += d_t[s];
        }
    }
#pragma unroll
    for (int o = 16; o; o >>= 1) a += __shfl_down_sync(0xffffffffu, a, o);
    if (lane == 0) d_score[d] = tanhf(a + brel[0] + d_r[d]);
}

// ---------------- top-k pool (block per graph, 512 threads) ----------------
__global__ __launch_bounds__(512) void k_pool(int xid, int K, int stage) {
    int g = blockIdx.x;
    int t = threadIdx.x;
    int tx = t & 127, ty = t >> 7;
    __shared__ float s[Nn];
    __shared__ unsigned char sel[Nn];
    {
        int n = g * Nn + t;
        s[t] = d_nmask[n] ? d_score[n] : -INFINITY;
    }
    __syncthreads();
    {
        float si = s[t];
        int rank = 0;
        for (int j = 0; j < Nn; j++) {
            float sj = s[j];
            rank += (sj > si) || ((sj == si) && (j < t));
        }
        int se = (rank < K) ? 1 : 0;
        sel[t] = (unsigned char)se;
        d_nmask[g * Nn + t] = (unsigned char)se;
    }
    __syncthreads();
    float* X = getbuf(xid, nullptr);
    float acc = 0.f;
    for (int n = ty; n < Nn; n += 4) {
        size_t idx = (size_t)(g * Nn + n) * FD + tx;
        float v = sel[n] ? X[idx] * s[n] : 0.f;
        X[idx] = v;
        acc += v;
    }
    __shared__ float gs[4][128];
    gs[ty][tx] = acc;
    __syncthreads();
    if (ty == 0)
        d_gap[stage * Bg * FD + g * FD + tx] =
            (gs[0][tx] + gs[1][tx] + gs[2][tx] + gs[3][tx]) / (float)K;
}

// ---------------- GAT ----------------
__global__ void k_vmat(const float* __restrict__ gwe, const float* __restrict__ gae) {  // <<<1,32>>>
    int lane = threadIdx.x;
    if (lane < 8) d_easum[lane] = 0.f;
    for (int o = 0; o < 28; o++) {
        int ed = o >> 2, h = o & 3;
        float p = gwe[ed * FD + h * 32 + lane] * gae[h * 32 + lane];
#pragma unroll
        for (int off = 16; off; off >>= 1) p += __shfl_down_sync(0xffffffffu, p, off);
        if (lane == 0) d_V[ed * 4 + h] = p;
    }
}

// merged: per-edge attention logits (d_ale) + masked edge_attr sums (d_easum)
// one pass over ea instead of two
__global__ void k_aleeasum(const float* __restrict__ ea, const int* __restrict__ src,
                           const int* __restrict__ dst) {
    float loc[8];
#pragma unroll
    for (int k = 0; k < 8; k++) loc[k] = 0.f;
    for (int e = blockIdx.x * blockDim.x + threadIdx.x; e < NE; e += gridDim.x * blockDim.x) {
        float at[7];
#pragma unroll
        for (int ed = 0; ed < 7; ed++) at[ed] = ea[(size_t)e * 7 + ed];
#pragma unroll
        for (int h = 0; h < 4; h++) {
            float a = 0.f;
#pragma unroll
            for (int ed = 0; ed < 7; ed++) a += at[ed] * d_V[ed * 4 + h];
            d_ale[(size_t)e * 4 + h] = a;
        }
        if (d_nmask[src[e]] && d_nmask[dst[e]]) {
#pragma unroll
            for (int ed = 0; ed < 7; ed++) loc[ed] += at[ed];
            loc[7] += 1.f;
        }
    }
    int lane = threadIdx.x & 31;
#pragma unroll
    for (int k = 0; k < 8; k++) {
        float v = loc[k];
#pragma unroll
        for (int o = 16; o; o >>= 1) v += __shfl_down_sync(0xffffffffu, v, o);
        if (lane == 0) atomicAdd(&d_easum[k], v);
    }
}

__global__ void k_alse() {  // <<<1,32>>>
    int lane = threadIdx.x;
    if (lane < 4) {
        float c = fmaxf(d_easum[7], 1.f);
        float a = 0.f;
#pragma unroll
        for (int ed = 0; ed < 7; ed++) a += (d_easum[ed] / c) * d_V[ed * 4 + lane];
        d_alse[lane] = a;
    }
}

// warp per dst; online softmax; each lane owns 4 columns of head (lane>>3);
// fused p3 score dots (d_t, d_r) in the epilogue
__global__ void k_gat(const float* __restrict__ gb,
                      const float* __restrict__ w1, const float* __restrict__ w2) {
    int d = (blockIdx.x * blockDim.x + threadIdx.x) >> 5;
    int lane = threadIdx.x & 31;
    if (d >= NBn) return;
    int h = lane >> 3;
    float m = -INFINITY, den = 0.f;
    float4 acc = make_float4(0.f, 0.f, 0.f, 0.f);
    bool dal = d_nmask[d] != 0;
    float aldL = (lane < 4) ? d_ald[d * 4 + lane] : 0.f;
    if (dal) {
        int b = d_rowptr[d], e2 = d_rowptr[d + 1];
        for (int i = b; i < e2; i++) {
            int2 se = d_se[i];
            int s = se.x;
            if (!d_nmask[s]) continue;
            int e = se.y;
            float tl = 0.f;
            if (lane < 4) {
                tl = d_als[s * 4 + lane] + aldL + d_ale[(size_t)e * 4 + lane];
                tl = tl > 0.f ? tl : 0.2f * tl;
            }
            float aj = __shfl_sync(0xffffffffu, tl, h);
            float4 xv = *(const float4*)(d_xs + (size_t)s * FD + lane * 4);
            if (aj > m) {
                float sc = __expf(m - aj);
                den = den * sc + 1.f;
                acc.x = acc.x * sc + xv.x;
                acc.y = acc.y * sc + xv.y;
                acc.z = acc.z * sc + xv.z;
                acc.w = acc.w * sc + xv.w;
                m = aj;
            } else {
                float c = __expf(aj - m);
                den += c;
                acc.x += c * xv.x;
                acc.y += c * xv.y;
                acc.z += c * xv.z;
                acc.w += c * xv.w;
            }
        }
        // self loop
        float tl = 0.f;
        if (lane < 4) {
            tl = d_als[d * 4 + lane] + aldL + d_alse[lane];
            tl = tl > 0.f ? tl : 0.2f * tl;
        }
        float aj = __shfl_sync(0xffffffffu, tl, h);
        float4 xv = *(const float4*)(d_xs + (size_t)d * FD + lane * 4);
        if (aj > m) {
            float sc = __expf(m - aj);
            den = den * sc + 1.f;
            acc.x = acc.x * sc + xv.x;
            acc.y = acc.y * sc + xv.y;
            acc.z = acc.z * sc + xv.z;
            acc.w = acc.w * sc + xv.w;
            m = aj;
        } else {
            float c = __expf(aj - m);
            den += c;
            acc.x += c * xv.x;
            acc.y += c * xv.y;
            acc.z += c * xv.z;
            acc.w += c * xv.w;
        }
    }
    float invd = 1.f / fmaxf(den, 1e-16f);
    float4 bb = *(const float4*)(gb + lane * 4);
    float4 o;
    o.x = fmaxf(acc.x * invd + bb.x, 0.f);
    o.y = fmaxf(acc.y * invd + bb.y, 0.f);
    o.z = fmaxf(acc.z * invd + bb.z, 0.f);
    o.w = fmaxf(acc.w * invd + bb.w, 0.f);
    *(float4*)(d_xc + (size_t)d * FD + lane * 4) = o;
    // fused p3 score dots
    float4 wv1 = *(const float4*)(w1 + lane * 4);
    float4 wv2 = *(const float4*)(w2 + lane * 4);
    float p1 = o.x * wv1.x + o.y * wv1.y + o.z * wv1.z + o.w * wv1.w;
    float p2 = o.x * wv2.x + o.y * wv2.y + o.z * wv2.z + o.w * wv2.w;
#pragma unroll
    for (int off = 16; off; off >>= 1) {
        p1 += __shfl_down_sync(0xffffffffu, p1, off);
        p2 += __shfl_down_sync(0xffffffffu, p2, off);
    }
    if (lane == 0) { d_t[d] = p1; d_r[d] = p2; }
}

// ---------------- head MLP (block per graph) ----------------
__global__ void k_head(const float* __restrict__ l1w, const float* __restrict__ l1b,
                       const float* __restrict__ l2w, const float* __restrict__ l2b,
                       const float* __restrict__ l3w, const float* __restrict__ l3b,
                       float* __restrict__ out) {
    int g = blockIdx.x;
    int t = threadIdx.x;
    __shared__ float h[128], h2[128], h3[64];
    h[t] = d_gap[g * FD + t] + d_gap[Bg * FD + g * FD + t] + d_gap[2 * Bg * FD + g * FD + t];
    __syncthreads();
    float a = l1b[t];
    for (int k = 0; k < 128; k++) a += h[k] * l1w[k * 128 + t];
    h2[t] = fmaxf(a, 0.f);
    __syncthreads();
    if (t < 64) {
        float a2 = l2b[t];
        for (int k = 0; k < 128; k++) a2 += h2[k] * l2w[k * 64 + t];
        h3[t] = fmaxf(a2, 0.f);
    }
    __syncthreads();
    if (t == 0) {
        float z = l3b[0];
        for (int k = 0; k < 64; k++) z += h3[k] * l3w[k];
        out[g] = 1.f / (1.f + expf(-z));
    }
}

// ---------------- launch ----------------
extern "C" void kernel_launch(void* const* d_in, const int* in_sizes, int n_in,
                              void* d_out, int out_size) {
    const float* x      = (const float*)d_in[0];
    const int*   ei     = (const int*)d_in[1];
    const float* ea     = (const float*)d_in[2];
    const float* c1_wl  = (const float*)d_in[3];
    const float* c1_bl  = (const float*)d_in[4];
    const float* c1_wr  = (const float*)d_in[5];
    const float* p1_w   = (const float*)d_in[6];
    const float* c2_wl  = (const float*)d_in[7];
    const float* c2_bl  = (const float*)d_in[8];
    const float* c2_wr  = (const float*)d_in[9];
    const float* p2_wrel= (const float*)d_in[10];
    const float* p2_brel= (const float*)d_in[11];
    const float* p2_wroot=(const float*)d_in[12];
    const float* g_w    = (const float*)d_in[13];
    const float* g_as   = (const float*)d_in[14];
    const float* g_ad   = (const float*)d_in[15];
    const float* g_we   = (const float*)d_in[16];
    const float* g_ae   = (const float*)d_in[17];
    const float* g_b    = (const float*)d_in[18];
    const float* p3_wrel= (const float*)d_in[19];
    const float* p3_brel= (const float*)d_in[20];
    const float* p3_wroot=(const float*)d_in[21];
    const float* l1_w   = (const float*)d_in[22];
    const float* l1_b   = (const float*)d_in[23];
    const float* l2_w   = (const float*)d_in[24];
    const float* l2_b   = (const float*)d_in[25];
    const float* l3_w   = (const float*)d_in[26];
    const float* l3_b   = (const float*)d_in[27];
    const int* src = ei;
    const int* dst = ei + NE;
    float* out = (float*)d_out;

    // CSR build (parallel 3-phase scan)
    k_init<<<NBn / 256, 256>>>();
    k_hist<<<NE / 256, 256>>>(dst);
    k_bsum<<<256, 256>>>();
    k_scanb<<<1, 256>>>();
    k_scan2<<<256, 256>>>();
    k_scatter<<<NE / 256, 256>>>(src, dst);
    k_p1norm<<<1, 128>>>(p1_w);

    // block 1: SAGE -> TopK(0.8) -> gap  (score fused in GEMM epilogue)
    k_aggmean<<<NBn / 8, 256>>>(5, x, 0);
    k_gemm<<<NBn / 64, 256>>>(0, nullptr, c1_wl, 5, x, c1_wr, c1_bl, 1, 8, 1,
                              nullptr, nullptr, p1_w, nullptr, 1);
    k_pool<<<Bg, 512>>>(1, KK1, 0);

    // block 2: SAGE -> SAGPool(0.5) -> gap  (t/r fused in GEMM epilogue)
    k_aggmean<<<NBn / 8, 256>>>(1, nullptr, 1);
    k_gemm<<<NBn / 64, 256>>>(0, nullptr, c2_wl, 1, nullptr, c2_wr, c2_bl, 2, 8, 1,
                              nullptr, nullptr, p2_wrel, p2_wroot, 2);
    k_gconv<<<NBn * 32 / 256, 256>>>(p2_brel);
    k_pool<<<Bg, 512>>>(2, KK2, 1);

    // block 3: GAT -> SAGPool(0.5) -> gap  (als/ald fused in GEMM, t/r fused in GAT,
    //                                       ale+easum merged into one edge pass)
    k_gemm<<<NBn / 64, 256>>>(2, nullptr, g_w, 0, nullptr, g_w, nullptr, 3, 4, 0,
                              g_as, g_ad, nullptr, nullptr, 0);
    k_vmat<<<1, 32>>>(g_we, g_ae);
    k_aleeasum<<<512, 256>>>(ea, src, dst);
    k_alse<<<1, 32>>>();
    k_gat<<<NBn * 32 / 256, 256>>>(g_b, p3_wrel, p3_wroot);
    k_gconv<<<NBn * 32 / 256, 256>>>(p3_brel);
    k_pool<<<Bg, 512>>>(4, KK3, 2);

    // head MLP
    k_head<<<Bg, 128>>>(l1_w, l1_b, l2_w, l2_b, l3_w, l3_b, out);
}

// round 16
// speedup vs baseline: 1.0612x; 1.0283x over previous
#include <cuda_runtime.h>
#include <math.h>
#include <stdint.h>

#define NBn 65536
#define NE  1048576
#define Bg  128
#define Nn  512
#define KK1 410
#define KK2 205
#define KK3 103
#define FD  128

// packed fp32x2 FMA: d = a*b + c on both halves (SASS FFMA2)
#define FMA_F32X2(d, a, b, c) \
    asm("fma.rn.f32x2 %0, %1, %2, %3;" : "=l"(d) : "l"(a), "l"(b), "l"(c))
#define PACK_F32X2(out, lo, hi) \
    asm("mov.b64 %0, {%1, %2};" : "=l"(out) : "f"(lo), "f"(hi))
#define UNPACK_F32X2(lo, hi, in) \
    asm("mov.b64 {%0, %1}, %2;" : "=f"(lo), "=f"(hi) : "l"(in))

// ---------------- device global scratch ----------------
__device__ float d_agg[NBn * FD];
__device__ float d_xa [NBn * FD];
__device__ float d_xb [NBn * FD];
__device__ float d_xs [NBn * FD];
__device__ float d_xc [NBn * FD];
__device__ float d_score[NBn];
__device__ float d_t[NBn];
__device__ float d_r[NBn];
__device__ unsigned char d_nmask[NBn];
__device__ int   d_hist[NBn];
__device__ int   d_rowptr[NBn + 1];
__device__ int   d_posA[NBn];
__device__ int   d_bsum[256];
__device__ int   d_bsumx[256];
__device__ int2  d_se[NE];
__device__ float d_als[NBn * 4];
__device__ float d_ald[NBn * 4];
__device__ float d_ale[(size_t)NE * 4];
__device__ float d_V[28];
__device__ float d_alse[4];
__device__ float d_easum[8];
__device__ float d_gap[3 * Bg * FD];
__device__ float d_p1norm;

__device__ __forceinline__ float* getbuf(int id, const float* ext) {
    switch (id) {
        case 0: return d_agg;
        case 1: return d_xa;
        case 2: return d_xb;
        case 3: return d_xs;
        case 4: return d_xc;
        default: return (float*)ext;
    }
}

// ---------------- init: hist=0, nmask=1 ----------------
__global__ void k_init() {
    int i = blockIdx.x * blockDim.x + threadIdx.x;
    if (i < NBn) { d_hist[i] = 0; d_nmask[i] = 1; }
}

// ---------------- CSR build ----------------
__global__ void k_hist(const int* __restrict__ dst) {
    int e = blockIdx.x * blockDim.x + threadIdx.x;
    if (e < NE) atomicAdd(&d_hist[dst[e]], 1);
}

__global__ void k_bsum() {
    int t = threadIdx.x;
    int v = d_hist[blockIdx.x * 256 + t];
    int lane = t & 31, w = t >> 5;
#pragma unroll
    for (int o = 16; o; o >>= 1) v += __shfl_down_sync(0xffffffffu, v, o);
    __shared__ int ws[8];
    if (lane == 0) ws[w] = v;
    __syncthreads();
    if (t == 0) {
        int s = 0;
#pragma unroll
        for (int i = 0; i < 8; i++) s += ws[i];
        d_bsum[blockIdx.x] = s;
    }
}

__global__ void k_scanb() {
    int t = threadIdx.x;
    int v = d_bsum[t];
    int lane = t & 31, w = t >> 5;
    int x = v;
#pragma unroll
    for (int o = 1; o < 32; o <<= 1) {
        int y = __shfl_up_sync(0xffffffffu, x, o);
        if (lane >= o) x += y;
    }
    __shared__ int ws[8];
    if (lane == 31) ws[w] = x;
    __syncthreads();
    __shared__ int wx[8];
    if (t == 0) {
        int run = 0;
#pragma unroll
        for (int i = 0; i < 8; i++) { wx[i] = run; run += ws[i]; }
    }
    __syncthreads();
    d_bsumx[t] = wx[w] + x - v;
    if (t == 0) d_rowptr[NBn] = NE;
}

__global__ void k_scan2() {
    int t = threadIdx.x;
    int i = blockIdx.x * 256 + t;
    int v = d_hist[i];
    int lane = t & 31, w = t >> 5;
    int x = v;
#pragma unroll
    for (int o = 1; o < 32; o <<= 1) {
        int y = __shfl_up_sync(0xffffffffu, x, o);
        if (lane >= o) x += y;
    }
    __shared__ int ws[8];
    if (lane == 31) ws[w] = x;
    __syncthreads();
    __shared__ int wx[8];
    if (t == 0) {
        int run = 0;
#pragma unroll
        for (int j = 0; j < 8; j++) { wx[j] = run; run += ws[j]; }
    }
    __syncthreads();
    int excl = d_bsumx[blockIdx.x] + wx[w] + x - v;
    d_rowptr[i] = excl;
    d_posA[i]   = excl;
}

__global__ void k_scatter(const int* __restrict__ src, const int* __restrict__ dst) {
    int e = blockIdx.x * blockDim.x + threadIdx.x;
    if (e >= NE) return;
    int p = atomicAdd(&d_posA[dst[e]], 1);
    d_se[p] = make_int2(src[e], e);
}

// ---------------- SAGE mean aggregation (warp per dst, unroll-2 float4) ----------------
__global__ void k_aggmean(int xid, const float* __restrict__ xext, int use_mask) {
    int w = (blockIdx.x * blockDim.x + threadIdx.x) >> 5;
    int lane = threadIdx.x & 31;
    if (w >= NBn) return;
    const float* X = getbuf(xid, xext);
    float4 a = make_float4(0.f, 0.f, 0.f, 0.f);
    float cnt = 0.f;
    if (!use_mask || d_nmask[w]) {
        int b = d_rowptr[w], e = d_rowptr[w + 1];
        int i = b;
        for (; i + 1 < e; i += 2) {
            int s0 = d_se[i].x, s1 = d_se[i + 1].x;
            bool l0 = !use_mask || d_nmask[s0];
            bool l1 = !use_mask || d_nmask[s1];
            float4 v0, v1;
            if (l0) v0 = *(const float4*)(X + (size_t)s0 * FD + lane * 4);
            if (l1) v1 = *(const float4*)(X + (size_t)s1 * FD + lane * 4);
            if (l0) { a.x += v0.x; a.y += v0.y; a.z += v0.z; a.w += v0.w; cnt += 1.f; }
            if (l1) { a.x += v1.x; a.y += v1.y; a.z += v1.z; a.w += v1.w; cnt += 1.f; }
        }
        if (i < e) {
            int s0 = d_se[i].x;
            if (!use_mask || d_nmask[s0]) {
                float4 v0 = *(const float4*)(X + (size_t)s0 * FD + lane * 4);
                a.x += v0.x; a.y += v0.y; a.z += v0.z; a.w += v0.w; cnt += 1.f;
            }
        }
    }
    float inv = 1.f / fmaxf(cnt, 1.f);
    a.x *= inv; a.y *= inv; a.z *= inv; a.w *= inv;
    *(float4*)(d_agg + (size_t)w * FD + lane * 4) = a;
}

// ---------------- GEMM with fused epilogues (R11-exact) ----------------
__global__ __launch_bounds__(256) void k_gemm(
    int a0id, const float* __restrict__ a0ext, const float* __restrict__ W0,
    int a1id, const float* __restrict__ a1ext, const float* __restrict__ W1,
    const float* __restrict__ bias, int cid, int ktiles, int dorelu,
    const float* __restrict__ as_w, const float* __restrict__ ad_w,
    const float* __restrict__ sw1, const float* __restrict__ sw2, int smode)
{
    __shared__ float As_t[32][66];
    __shared__ float Bs[32][128];
    int tid = threadIdx.x;
    int m0 = blockIdx.x * 64;
    int cx = tid & 31, ry = tid >> 5;

    unsigned long long acc[4][4];
    {
        unsigned long long z;
        PACK_F32X2(z, 0.f, 0.f);
#pragma unroll
        for (int p = 0; p < 4; p++)
#pragma unroll
            for (int j = 0; j < 4; j++) acc[p][j] = z;
    }

    for (int kt = 0; kt < ktiles; kt++) {
        const float* A; const float* W; int kl;
        if (kt < 4) { A = getbuf(a0id, a0ext); W = W0; kl = kt * 32; }
        else        { A = getbuf(a1id, a1ext); W = W1; kl = (kt - 4) * 32; }
#pragma unroll
        for (int r = 0; r < 2; r++) {
            int id = tid + 256 * r;
            int m = id >> 3, k4 = id & 7;
            float4 v = *(const float4*)&A[(size_t)(m0 + m) * FD + kl + k4 * 4];
            As_t[k4 * 4 + 0][m] = v.x;
            As_t[k4 * 4 + 1][m] = v.y;
            As_t[k4 * 4 + 2][m] = v.z;
            As_t[k4 * 4 + 3][m] = v.w;
        }
#pragma unroll
        for (int r = 0; r < 16; r++) {
            int id = tid + 256 * r;
            int kk = id >> 7, n = id & 127;
            Bs[kk][n] = W[(size_t)(kl + kk) * FD + n];
        }
        __syncthreads();
#pragma unroll
        for (int kk = 0; kk < 32; kk++) {
            float4 bv = *(const float4*)&Bs[kk][cx * 4];
            unsigned long long bb0, bb1, bb2, bb3;
            PACK_F32X2(bb0, bv.x, bv.x);
            PACK_F32X2(bb1, bv.y, bv.y);
            PACK_F32X2(bb2, bv.z, bv.z);
            PACK_F32X2(bb3, bv.w, bv.w);
#pragma unroll
            for (int p = 0; p < 4; p++) {
                unsigned long long aa =
                    *(const unsigned long long*)&As_t[kk][ry * 8 + 2 * p];
                FMA_F32X2(acc[p][0], aa, bb0, acc[p][0]);
                FMA_F32X2(acc[p][1], aa, bb1, acc[p][1]);
                FMA_F32X2(acc[p][2], aa, bb2, acc[p][2]);
                FMA_F32X2(acc[p][3], aa, bb3, acc[p][3]);
            }
        }
        __syncthreads();
    }
    int c0 = cx * 4;
    float b0 = 0.f, b1 = 0.f, b2 = 0.f, b3 = 0.f;
    if (bias) { b0 = bias[c0]; b1 = bias[c0 + 1]; b2 = bias[c0 + 2]; b3 = bias[c0 + 3]; }
    float aw0 = 0.f, aw1 = 0.f, aw2 = 0.f, aw3 = 0.f, dw0 = 0.f, dw1 = 0.f, dw2 = 0.f, dw3 = 0.f;
    if (as_w) {
        aw0 = as_w[c0]; aw1 = as_w[c0 + 1]; aw2 = as_w[c0 + 2]; aw3 = as_w[c0 + 3];
        dw0 = ad_w[c0]; dw1 = ad_w[c0 + 1]; dw2 = ad_w[c0 + 2]; dw3 = ad_w[c0 + 3];
    }
    float s10 = 0.f, s11 = 0.f, s12 = 0.f, s13 = 0.f, s20 = 0.f, s21 = 0.f, s22 = 0.f, s23 = 0.f;
    if (smode) {
        s10 = sw1[c0]; s11 = sw1[c0 + 1]; s12 = sw1[c0 + 2]; s13 = sw1[c0 + 3];
        if (smode == 2) { s20 = sw2[c0]; s21 = sw2[c0 + 1]; s22 = sw2[c0 + 2]; s23 = sw2[c0 + 3]; }
    }
    int h = cx >> 3;
    float* C = getbuf(cid, nullptr);
#pragma unroll
    for (int p = 0; p < 4; p++) {
        size_t me = m0 + ry * 8 + 2 * p;
        float4 oe, oo;
        UNPACK_F32X2(oe.x, oo.x, acc[p][0]);
        UNPACK_F32X2(oe.y, oo.y, acc[p][1]);
        UNPACK_F32X2(oe.z, oo.z, acc[p][2]);
        UNPACK_F32X2(oe.w, oo.w, acc[p][3]);
        oe.x += b0; oe.y += b1; oe.z += b2; oe.w += b3;
        oo.x += b0; oo.y += b1; oo.z += b2; oo.w += b3;
        if (dorelu) {
            oe.x = fmaxf(oe.x, 0.f); oe.y = fmaxf(oe.y, 0.f);
            oe.z = fmaxf(oe.z, 0.f); oe.w = fmaxf(oe.w, 0.f);
            oo.x = fmaxf(oo.x, 0.f); oo.y = fmaxf(oo.y, 0.f);
            oo.z = fmaxf(oo.z, 0.f); oo.w = fmaxf(oo.w, 0.f);
        }
        *(float4*)&C[me * FD + c0] = oe;
        *(float4*)&C[(me + 1) * FD + c0] = oo;
        if (as_w) {
            float pae = oe.x * aw0 + oe.y * aw1 + oe.z * aw2 + oe.w * aw3;
            float pao = oo.x * aw0 + oo.y * aw1 + oo.z * aw2 + oo.w * aw3;
            float pde = oe.x * dw0 + oe.y * dw1 + oe.z * dw2 + oe.w * dw3;
            float pdo = oo.x * dw0 + oo.y * dw1 + oo.z * dw2 + oo.w * dw3;
#pragma unroll
            for (int o = 4; o; o >>= 1) {
                pae += __shfl_down_sync(0xffffffffu, pae, o, 8);
                pao += __shfl_down_sync(0xffffffffu, pao, o, 8);
                pde += __shfl_down_sync(0xffffffffu, pde, o, 8);
                pdo += __shfl_down_sync(0xffffffffu, pdo, o, 8);
            }
            if ((cx & 7) == 0) {
                d_als[me * 4 + h] = pae;
                d_als[(me + 1) * 4 + h] = pao;
                d_ald[me * 4 + h] = pde;
                d_ald[(me + 1) * 4 + h] = pdo;
            }
        }
        if (smode) {
            float p1e = oe.x * s10 + oe.y * s11 + oe.z * s12 + oe.w * s13;
            float p1o = oo.x * s10 + oo.y * s11 + oo.z * s12 + oo.w * s13;
            float p2e = oe.x * s20 + oe.y * s21 + oe.z * s22 + oe.w * s23;
            float p2o = oo.x * s20 + oo.y * s21 + oo.z * s22 + oo.w * s23;
#pragma unroll
            for (int o = 16; o; o >>= 1) {
                p1e += __shfl_down_sync(0xffffffffu, p1e, o);
                p1o += __shfl_down_sync(0xffffffffu, p1o, o);
                p2e += __shfl_down_sync(0xffffffffu, p2e, o);
                p2o += __shfl_down_sync(0xffffffffu, p2o, o);
            }
            if (cx == 0) {
                if (smode == 1) {
                    float inv = 1.f / d_p1norm;
                    d_score[me] = tanhf(p1e * inv);
                    d_score[me + 1] = tanhf(p1o * inv);
                } else {
                    d_t[me] = p1e; d_t[me + 1] = p1o;
                    d_r[me] = p2e; d_r[me + 1] = p2o;
                }
            }
        }
    }
}

__global__ void k_p1norm(const float* __restrict__ w) {  // <<<1,128>>>
    __shared__ float sm[128];
    int t = threadIdx.x;
    float v = w[t];
    sm[t] = v * v;
    __syncthreads();
    for (int o = 64; o; o >>= 1) { if (t < o) sm[t] += sm[t + o]; __syncthreads(); }
    if (t == 0) d_p1norm = sqrtf(sm[0]);
}

// GraphConv score: tanh( sum_{live e->d} t[src] + brel + r[d] )
__global__ void k_gconv(const float* __restrict__ brel) {
    int d = (blockIdx.x * blockDim.x + threadIdx.x) >> 5;
    int lane = threadIdx.x & 31;
    if (d >= NBn) return;
    float a = 0.f;
    if (d_nmask[d]) {
        int b = d_rowptr[d], e = d_rowptr[d + 1];
        for (int i = b + lane; i < e; i += 32) {
            int s = d_se[i].x;
            if (d_nmask[s]) a += d_t[s];
        }
    }
#pragma unroll
    for (int o = 16; o; o >>= 1) a += __shfl_down_sync(0xffffffffu, a, o);
    if (lane == 0) d_score[d] = tanhf(a + brel[0] + d_r[d]);
}

// ---------------- top-k pool (block per graph, 512 threads) ----------------
__global__ __launch_bounds__(512) void k_pool(int xid, int K, int stage) {
    int g = blockIdx.x;
    int t = threadIdx.x;
    int tx = t & 127, ty = t >> 7;
    __shared__ float s[Nn];
    __shared__ unsigned char sel[Nn];
    {
        int n = g * Nn + t;
        s[t] = d_nmask[n] ? d_score[n] : -INFINITY;
    }
    __syncthreads();
    {
        float si = s[t];
        int rank = 0;
        for (int j = 0; j < Nn; j++) {
            float sj = s[j];
            rank += (sj > si) || ((sj == si) && (j < t));
        }
        int se = (rank < K) ? 1 : 0;
        sel[t] = (unsigned char)se;
        d_nmask[g * Nn + t] = (unsigned char)se;
    }
    __syncthreads();
    float* X = getbuf(xid, nullptr);
    float acc = 0.f;
    for (int n = ty; n < Nn; n += 4) {
        size_t idx = (size_t)(g * Nn + n) * FD + tx;
        float v = sel[n] ? X[idx] * s[n] : 0.f;
        X[idx] = v;
        acc += v;
    }
    __shared__ float gs[4][128];
    gs[ty][tx] = acc;
    __syncthreads();
    if (ty == 0)
        d_gap[stage * Bg * FD + g * FD + tx] =
            (gs[0][tx] + gs[1][tx] + gs[2][tx] + gs[3][tx]) / (float)K;
}

// ---------------- GAT ----------------
__global__ void k_vmat(const float* __restrict__ gwe, const float* __restrict__ gae) {  // <<<1,32>>>
    int lane = threadIdx.x;
    if (lane < 8) d_easum[lane] = 0.f;
    for (int o = 0; o < 28; o++) {
        int ed = o >> 2, h = o & 3;
        float p = gwe[ed * FD + h * 32 + lane] * gae[h * 32 + lane];
#pragma unroll
        for (int off = 16; off; off >>= 1) p += __shfl_down_sync(0xffffffffu, p, off);
        if (lane == 0) d_V[ed * 4 + h] = p;
    }
}

// merged: per-edge logits + masked edge_attr sums, single pass over ea
__global__ void k_aleeasum(const float* __restrict__ ea, const int* __restrict__ src,
                           const int* __restrict__ dst) {
    float loc[8];
#pragma unroll
    for (int k = 0; k < 8; k++) loc[k] = 0.f;
    for (int e = blockIdx.x * blockDim.x + threadIdx.x; e < NE; e += gridDim.x * blockDim.x) {
        float at[7];
#pragma unroll
        for (int ed = 0; ed < 7; ed++) at[ed] = ea[(size_t)e * 7 + ed];
#pragma unroll
        for (int h = 0; h < 4; h++) {
            float a = 0.f;
#pragma unroll
            for (int ed = 0; ed < 7; ed++) a += at[ed] * d_V[ed * 4 + h];
            d_ale[(size_t)e * 4 + h] = a;
        }
        if (d_nmask[src[e]] && d_nmask[dst[e]]) {
#pragma unroll
            for (int ed = 0; ed < 7; ed++) loc[ed] += at[ed];
            loc[7] += 1.f;
        }
    }
    int lane = threadIdx.x & 31;
#pragma unroll
    for (int k = 0; k < 8; k++) {
        float v = loc[k];
#pragma unroll
        for (int o = 16; o; o >>= 1) v += __shfl_down_sync(0xffffffffu, v, o);
        if (lane == 0) atomicAdd(&d_easum[k], v);
    }
}

__global__ void k_alse() {  // <<<1,32>>>
    int lane = threadIdx.x;
    if (lane < 4) {
        float c = fmaxf(d_easum[7], 1.f);
        float a = 0.f;
#pragma unroll
        for (int ed = 0; ed < 7; ed++) a += (d_easum[ed] / c) * d_V[ed * 4 + lane];
        d_alse[lane] = a;
    }
}

// warp per dst; online softmax; each lane owns 4 columns of head (lane>>3);
// fused p3 score dots (d_t, d_r) in the epilogue
__global__ void k_gat(const float* __restrict__ gb,
                      const float* __restrict__ w1, const float* __restrict__ w2) {
    int d = (blockIdx.x * blockDim.x + threadIdx.x) >> 5;
    int lane = threadIdx.x & 31;
    if (d >= NBn) return;
    int h = lane >> 3;
    float m = -INFINITY, den = 0.f;
    float4 acc = make_float4(0.f, 0.f, 0.f, 0.f);
    bool dal = d_nmask[d] != 0;
    float aldL = (lane < 4) ? d_ald[d * 4 + lane] : 0.f;
    if (dal) {
        int b = d_rowptr[d], e2 = d_rowptr[d + 1];
        for (int i = b; i < e2; i++) {
            int2 se = d_se[i];
            int s = se.x;
            if (!d_nmask[s]) continue;
            int e = se.y;
            float tl = 0.f;
            if (lane < 4) {
                tl = d_als[s * 4 + lane] + aldL + d_ale[(size_t)e * 4 + lane];
                tl = tl > 0.f ? tl : 0.2f * tl;
            }
            float aj = __shfl_sync(0xffffffffu, tl, h);
            float4 xv = *(const float4*)(d_xs + (size_t)s * FD + lane * 4);
            if (aj > m) {
                float sc = __expf(m - aj);
                den = den * sc + 1.f;
                acc.x = acc.x * sc + xv.x;
                acc.y = acc.y * sc + xv.y;
                acc.z = acc.z * sc + xv.z;
                acc.w = acc.w * sc + xv.w;
                m = aj;
            } else {
                float c = __expf(aj - m);
                den += c;
                acc.x += c * xv.x;
                acc.y += c * xv.y;
                acc.z += c * xv.z;
                acc.w += c * xv.w;
            }
        }
        // self loop
        float tl = 0.f;
        if (lane < 4) {
            tl = d_als[d * 4 + lane] + aldL + d_alse[lane];
            tl = tl > 0.f ? tl : 0.2f * tl;
        }
        float aj = __shfl_sync(0xffffffffu, tl, h);
        float4 xv = *(const float4*)(d_xs + (size_t)d * FD + lane * 4);
        if (aj > m) {
            float sc = __expf(m - aj);
            den = den * sc + 1.f;
            acc.x = acc.x * sc + xv.x;
            acc.y = acc.y * sc + xv.y;
            acc.z = acc.z * sc + xv.z;
            acc.w = acc.w * sc + xv.w;
            m = aj;
        } else {
            float c = __expf(aj - m);
            den += c;
            acc.x += c * xv.x;
            acc.y += c * xv.y;
            acc.z += c * xv.z;
            acc.w += c * xv.w;
        }
    }
    float invd = 1.f / fmaxf(den, 1e-16f);
    float4 bb = *(const float4*)(gb + lane * 4);
    float4 o;
    o.x = fmaxf(acc.x * invd + bb.x, 0.f);
    o.y = fmaxf(acc.y * invd + bb.y, 0.f);
    o.z = fmaxf(acc.z * invd + bb.z, 0.f);
    o.w = fmaxf(acc.w * invd + bb.w, 0.f);
    *(float4*)(d_xc + (size_t)d * FD + lane * 4) = o;
    float4 wv1 = *(const float4*)(w1 + lane * 4);
    float4 wv2 = *(const float4*)(w2 + lane * 4);
    float p1 = o.x * wv1.x + o.y * wv1.y + o.z * wv1.z + o.w * wv1.w;
    float p2 = o.x * wv2.x + o.y * wv2.y + o.z * wv2.z + o.w * wv2.w;
#pragma unroll
    for (int off = 16; off; off >>= 1) {
        p1 += __shfl_down_sync(0xffffffffu, p1, off);
        p2 += __shfl_down_sync(0xffffffffu, p2, off);
    }
    if (lane == 0) { d_t[d] = p1; d_r[d] = p2; }
}

// ---------------- head MLP (block per graph) ----------------
__global__ void k_head(const float* __restrict__ l1w, const float* __restrict__ l1b,
                       const float* __restrict__ l2w, const float* __restrict__ l2b,
                       const float* __restrict__ l3w, const float* __restrict__ l3b,
                       float* __restrict__ out) {
    int g = blockIdx.x;
    int t = threadIdx.x;
    __shared__ float h[128], h2[128], h3[64];
    h[t] = d_gap[g * FD + t] + d_gap[Bg * FD + g * FD + t] + d_gap[2 * Bg * FD + g * FD + t];
    __syncthreads();
    float a = l1b[t];
    for (int k = 0; k < 128; k++) a += h[k] * l1w[k * 128 + t];
    h2[t] = fmaxf(a, 0.f);
    __syncthreads();
    if (t < 64) {
        float a2 = l2b[t];
        for (int k = 0; k < 128; k++) a2 += h2[k] * l2w[k * 64 + t];
        h3[t] = fmaxf(a2, 0.f);
    }
    __syncthreads();
    if (t == 0) {
        float z = l3b[0];
        for (int k = 0; k < 64; k++) z += h3[k] * l3w[k];
        out[g] = 1.f / (1.f + expf(-z));
    }
}

// ---------------- launch ----------------
extern "C" void kernel_launch(void* const* d_in, const int* in_sizes, int n_in,
                              void* d_out, int out_size) {
    const float* x      = (const float*)d_in[0];
    const int*   ei     = (const int*)d_in[1];
    const float* ea     = (const float*)d_in[2];
    const float* c1_wl  = (const float*)d_in[3];
    const float* c1_bl  = (const float*)d_in[4];
    const float* c1_wr  = (const float*)d_in[5];
    const float* p1_w   = (const float*)d_in[6];
    const float* c2_wl  = (const float*)d_in[7];
    const float* c2_bl  = (const float*)d_in[8];
    const float* c2_wr  = (const float*)d_in[9];
    const float* p2_wrel= (const float*)d_in[10];
    const float* p2_brel= (const float*)d_in[11];
    const float* p2_wroot=(const float*)d_in[12];
    const float* g_w    = (const float*)d_in[13];
    const float* g_as   = (const float*)d_in[14];
    const float* g_ad   = (const float*)d_in[15];
    const float* g_we   = (const float*)d_in[16];
    const float* g_ae   = (const float*)d_in[17];
    const float* g_b    = (const float*)d_in[18];
    const float* p3_wrel= (const float*)d_in[19];
    const float* p3_brel= (const float*)d_in[20];
    const float* p3_wroot=(const float*)d_in[21];
    const float* l1_w   = (const float*)d_in[22];
    const float* l1_b   = (const float*)d_in[23];
    const float* l2_w   = (const float*)d_in[24];
    const float* l2_b   = (const float*)d_in[25];
    const float* l3_w   = (const float*)d_in[26];
    const float* l3_b   = (const float*)d_in[27];
    const int* src = ei;
    const int* dst = ei + NE;
    float* out = (float*)d_out;

    // side stream + events for block-3 fork/join (created per call; capture
    // absorbs the side stream, replays run the fork concurrently)
    cudaStream_t s2;
    cudaEvent_t evF, evJ;
    cudaStreamCreateWithFlags(&s2, cudaStreamNonBlocking);
    cudaEventCreateWithFlags(&evF, cudaEventDisableTiming);
    cudaEventCreateWithFlags(&evJ, cudaEventDisableTiming);

    // CSR build (parallel 3-phase scan)
    k_init<<<NBn / 256, 256>>>();
    k_hist<<<NE / 256, 256>>>(dst);
    k_bsum<<<256, 256>>>();
    k_scanb<<<1, 256>>>();
    k_scan2<<<256, 256>>>();
    k_scatter<<<NE / 256, 256>>>(src, dst);
    k_p1norm<<<1, 128>>>(p1_w);

    // block 1: SAGE -> TopK(0.8) -> gap  (score fused in GEMM epilogue)
    k_aggmean<<<NBn / 8, 256>>>(5, x, 0);
    k_gemm<<<NBn / 64, 256>>>(0, nullptr, c1_wl, 5, x, c1_wr, c1_bl, 1, 8, 1,
                              nullptr, nullptr, p1_w, nullptr, 1);
    k_pool<<<Bg, 512>>>(1, KK1, 0);

    // block 2: SAGE -> SAGPool(0.5) -> gap  (t/r fused in GEMM epilogue)
    k_aggmean<<<NBn / 8, 256>>>(1, nullptr, 1);
    k_gemm<<<NBn / 64, 256>>>(0, nullptr, c2_wl, 1, nullptr, c2_wr, c2_bl, 2, 8, 1,
                              nullptr, nullptr, p2_wrel, p2_wroot, 2);
    k_gconv<<<NBn * 32 / 256, 256>>>(p2_brel);
    k_pool<<<Bg, 512>>>(2, KK2, 1);

    // block 3: fork — edge-attr chain (s2) runs concurrently with the GAT GEMM (main)
    cudaEventRecord(evF, 0);
    cudaStreamWaitEvent(s2, evF, 0);
    k_vmat<<<1, 32, 0, s2>>>(g_we, g_ae);
    k_aleeasum<<<512, 256, 0, s2>>>(ea, src, dst);
    k_alse<<<1, 32, 0, s2>>>();
    cudaEventRecord(evJ, s2);

    k_gemm<<<NBn / 64, 256>>>(2, nullptr, g_w, 0, nullptr, g_w, nullptr, 3, 4, 0,
                              g_as, g_ad, nullptr, nullptr, 0);
    cudaStreamWaitEvent(0, evJ, 0);

    k_gat<<<NBn * 32 / 256, 256>>>(g_b, p3_wrel, p3_wroot);
    k_gconv<<<NBn * 32 / 256, 256>>>(p3_brel);
    k_pool<<<Bg, 512>>>(4, KK3, 2);

    // head MLP
    k_head<<<Bg, 128>>>(l1_w, l1_b, l2_w, l2_b, l3_w, l3_b, out);
}